// round 4
// baseline (speedup 1.0000x reference)
#include <cuda_runtime.h>
#include <math.h>

#define NL     32
#define NB     128
#define NPQ    40
#define NTHR   1024

typedef unsigned long long u64;

// ---------------------------------------------------------------------------
// gate tables (compile-time).  bit position = 9 - wire.
// type: 0 = RY (PA = bit pos), 1 = CRX (PA = control bit, PB = target bit)
// ---------------------------------------------------------------------------
constexpr int G_TYPE[40] = {0,0,0,0,0,0,0,0,0,0, 1,1,1,1,1,1,1,1,1,1,
                            0,0,0,0,0,0,0,0,0,0, 1,1,1,1,1,1,1,1,1,1};
constexpr int G_PA[40]   = {9,8,7,6,5,4,3,2,1,0, 0,1,2,3,4,5,6,7,8,9,
                            9,8,7,6,5,4,3,2,1,0, 0,9,8,7,6,5,4,3,2,1};
constexpr int G_PB[40]   = {0,0,0,0,0,0,0,0,0,0, 9,0,1,2,3,4,5,6,7,8,
                            0,0,0,0,0,0,0,0,0,0, 1,0,9,8,7,6,5,4,3,2};

// ---------------------------------------------------------------------------
// f32x2 helpers
// ---------------------------------------------------------------------------
__device__ __forceinline__ u64 F2(float2 v) {
    u64 r; asm("mov.b64 %0, {%1,%2};" : "=l"(r) : "f"(v.x), "f"(v.y)); return r;
}
__device__ __forceinline__ float2 U2(u64 v) {
    float2 p; asm("mov.b64 {%0,%1}, %2;" : "=f"(p.x), "=f"(p.y) : "l"(v)); return p;
}
__device__ __forceinline__ u64 fma2(u64 a, u64 b, u64 c) {
    u64 d; asm("fma.rn.f32x2 %0, %1, %2, %3;" : "=l"(d) : "l"(a), "l"(b), "l"(c)); return d;
}
__device__ __forceinline__ u64 mul2(u64 a, u64 b) {
    u64 d; asm("mul.rn.f32x2 %0, %1, %2;" : "=l"(d) : "l"(a), "l"(b)); return d;
}
__device__ __forceinline__ u64 add2(u64 a, u64 b) {
    u64 d; asm("add.rn.f32x2 %0, %1, %2;" : "=l"(d) : "l"(a), "l"(b)); return d;
}
template<int M>
__device__ __forceinline__ u64 shfl2(u64 v) {
    float2 t = U2(v);
    t.x = __shfl_xor_sync(0xffffffffu, t.x, M);
    t.y = __shfl_xor_sync(0xffffffffu, t.y, M);
    return F2(t);
}
__device__ __forceinline__ u64 swap2(u64 v) {
    float2 t = U2(v);
    return F2(make_float2(t.y, t.x));
}

// ---------------------------------------------------------------------------
// state layout: each PAIR of warps (w, w^1) holds one 1024-amp state.
//   amp = (wb<<9) | (pack<<8) | (v<<5) | lane
//   warp holds X[8], Y[8] (u64): X[v] packs (x@pack0, x@pack1)
//   bit P<5 -> lane (shfl); P in 5..7 -> v bit (P-5); P==8 -> pack (swap2);
//   P==9 -> warp bit (smem exchange, or free when it's a CRX control)
// ---------------------------------------------------------------------------

// ---- RY on lane bit ----
template<int P>
__device__ __forceinline__ void ry_lane(u64 (&X)[8], u64 (&Y)[8], float c, float s, unsigned lane) {
    const float sg = ((lane >> P) & 1u) ? s : -s;
    const u64 cc = F2(make_float2(c, c)), sg2 = F2(make_float2(sg, sg));
#pragma unroll
    for (int v = 0; v < 8; ++v) {
        X[v] = fma2(sg2, shfl2<(1 << P)>(X[v]), mul2(cc, X[v]));
        Y[v] = fma2(sg2, shfl2<(1 << P)>(Y[v]), mul2(cc, Y[v]));
    }
}
// ---- RY on v bit ----
template<int RB>
__device__ __forceinline__ void ry_reg(u64 (&X)[8], u64 (&Y)[8], float c, float s) {
    const u64 cc = F2(make_float2(c, c));
    const u64 sp = F2(make_float2(s, s)), sn = F2(make_float2(-s, -s));
#pragma unroll
    for (int v0 = 0; v0 < 8; ++v0) {
        if (v0 & (1 << RB)) continue;
        const int v1 = v0 | (1 << RB);
        u64 a0x = X[v0], a1x = X[v1], a0y = Y[v0], a1y = Y[v1];
        X[v0] = fma2(sn, a1x, mul2(cc, a0x));
        X[v1] = fma2(sp, a0x, mul2(cc, a1x));
        Y[v0] = fma2(sn, a1y, mul2(cc, a0y));
        Y[v1] = fma2(sp, a0y, mul2(cc, a1y));
    }
}
// ---- RY on pack bit ----
__device__ __forceinline__ void ry_pack(u64 (&X)[8], u64 (&Y)[8], float c, float s) {
    const u64 cc = F2(make_float2(c, c)), sv = F2(make_float2(-s, s));
#pragma unroll
    for (int v = 0; v < 8; ++v) {
        X[v] = fma2(sv, swap2(X[v]), mul2(cc, X[v]));
        Y[v] = fma2(sv, swap2(Y[v]), mul2(cc, Y[v]));
    }
}
// ---- RY on warp bit: smem exchange ----
__device__ __forceinline__ void ry_warp(u64 (&X)[8], u64 (&Y)[8], float c, float s,
                                        u64* buf, int tid, int ptid, int wb) {
#pragma unroll
    for (int i = 0; i < 8; ++i) buf[i * NTHR + tid] = X[i];
#pragma unroll
    for (int i = 0; i < 8; ++i) buf[(8 + i) * NTHR + tid] = Y[i];
    __syncthreads();
    const float sg = wb ? s : -s;
    const u64 sg2 = F2(make_float2(sg, sg)), cc = F2(make_float2(c, c));
#pragma unroll
    for (int i = 0; i < 8; ++i) X[i] = fma2(sg2, buf[i * NTHR + ptid], mul2(cc, X[i]));
#pragma unroll
    for (int i = 0; i < 8; ++i) Y[i] = fma2(sg2, buf[(8 + i) * NTHR + ptid], mul2(cc, Y[i]));
    __syncthreads();
}

// ---- RX (uncontrolled / locally-controlled) on target B (B != 9), full coeffs ----
template<int B>
__device__ __forceinline__ void rx_local(u64 (&X)[8], u64 (&Y)[8], float c, float s) {
    const u64 ce2 = F2(make_float2(c, c));
    const u64 se2 = F2(make_float2(s, s)), sn2 = F2(make_float2(-s, -s));
    if constexpr (B < 5) {
#pragma unroll
        for (int v = 0; v < 8; ++v) {
            u64 px = shfl2<(1 << B)>(X[v]);
            u64 py = shfl2<(1 << B)>(Y[v]);
            X[v] = fma2(se2, py, mul2(ce2, X[v]));
            Y[v] = fma2(sn2, px, mul2(ce2, Y[v]));
        }
    } else if constexpr (B < 8) {
        constexpr int TB = 1 << (B - 5);
#pragma unroll
        for (int v0 = 0; v0 < 8; ++v0) {
            if (v0 & TB) continue;
            const int v1 = v0 | TB;
            u64 a0x = X[v0], a0y = Y[v0], a1x = X[v1], a1y = Y[v1];
            X[v0] = fma2(se2, a1y, mul2(ce2, a0x));
            Y[v0] = fma2(sn2, a1x, mul2(ce2, a0y));
            X[v1] = fma2(se2, a0y, mul2(ce2, a1x));
            Y[v1] = fma2(sn2, a0x, mul2(ce2, a1y));
        }
    } else {  // B == 8
#pragma unroll
        for (int v = 0; v < 8; ++v) {
            u64 sx = swap2(X[v]), sy = swap2(Y[v]);
            X[v] = fma2(se2, sy, mul2(ce2, X[v]));
            Y[v] = fma2(sn2, sx, mul2(ce2, Y[v]));
        }
    }
}

// ---- CRX, control A (A != 9), target B (B != 9) ----
template<int A, int B>
__device__ __forceinline__ void crx_gate(u64 (&X)[8], u64 (&Y)[8], float c, float s, unsigned lane) {
    float2 cef, sef;
    if constexpr (A < 5) {
        const int cb = (lane >> A) & 1u;
        const float ce = cb ? c : 1.0f, se = cb ? s : 0.0f;
        cef = make_float2(ce, ce); sef = make_float2(se, se);
    } else if constexpr (A == 8) {
        cef = make_float2(1.0f, c); sef = make_float2(0.0f, s);
    } else {
        cef = make_float2(c, c); sef = make_float2(s, s);
    }
    const u64 ce2 = F2(cef), se2 = F2(sef), sn2 = F2(make_float2(-sef.x, -sef.y));
    constexpr bool vctrl = (A >= 5 && A < 8);
    constexpr int CB = vctrl ? (1 << (A - 5)) : 0;

    if constexpr (B < 5) {
#pragma unroll
        for (int v = 0; v < 8; ++v) {
            if (vctrl && !(v & CB)) continue;
            u64 px = shfl2<(1 << B)>(X[v]);
            u64 py = shfl2<(1 << B)>(Y[v]);
            X[v] = fma2(se2, py, mul2(ce2, X[v]));
            Y[v] = fma2(sn2, px, mul2(ce2, Y[v]));
        }
    } else if constexpr (B < 8) {
        constexpr int TB = 1 << (B - 5);
#pragma unroll
        for (int v0 = 0; v0 < 8; ++v0) {
            if (v0 & TB) continue;
            if (vctrl && !(v0 & CB)) continue;
            const int v1 = v0 | TB;
            u64 a0x = X[v0], a0y = Y[v0], a1x = X[v1], a1y = Y[v1];
            X[v0] = fma2(se2, a1y, mul2(ce2, a0x));
            Y[v0] = fma2(sn2, a1x, mul2(ce2, a0y));
            X[v1] = fma2(se2, a0y, mul2(ce2, a1x));
            Y[v1] = fma2(sn2, a0x, mul2(ce2, a1y));
        }
    } else {  // B == 8 pack target
#pragma unroll
        for (int v = 0; v < 8; ++v) {
            if (vctrl && !(v & CB)) continue;
            u64 sx = swap2(X[v]), sy = swap2(Y[v]);
            X[v] = fma2(se2, sy, mul2(ce2, X[v]));
            Y[v] = fma2(sn2, sx, mul2(ce2, Y[v]));
        }
    }
}

// ---- CRX with target = warp bit: smem exchange, coeffs by control A ----
template<int A>
__device__ __forceinline__ void crx_warp_tgt(u64 (&X)[8], u64 (&Y)[8], float c, float s,
                                             unsigned lane, u64* buf, int tid, int ptid) {
    float2 cef, sef;
    if constexpr (A < 5) {
        const int cb = (lane >> A) & 1u;
        const float ce = cb ? c : 1.0f, se = cb ? s : 0.0f;
        cef = make_float2(ce, ce); sef = make_float2(se, se);
    } else if constexpr (A == 8) {
        cef = make_float2(1.0f, c); sef = make_float2(0.0f, s);
    } else {
        cef = make_float2(c, c); sef = make_float2(s, s);
    }
    const u64 ce2 = F2(cef), se2 = F2(sef), sn2 = F2(make_float2(-sef.x, -sef.y));
#pragma unroll
    for (int i = 0; i < 8; ++i) buf[i * NTHR + tid] = X[i];
#pragma unroll
    for (int i = 0; i < 8; ++i) buf[(8 + i) * NTHR + tid] = Y[i];
    __syncthreads();
#pragma unroll
    for (int i = 0; i < 8; ++i) {
        u64 px = buf[i * NTHR + ptid];
        u64 py = buf[(8 + i) * NTHR + ptid];
        X[i] = fma2(se2, py, mul2(ce2, X[i]));
        Y[i] = fma2(sn2, px, mul2(ce2, Y[i]));
    }
    __syncthreads();
}

// ---- dispatcher ----
template<int K>
__device__ __forceinline__ void do_gate(u64 (&X)[8], u64 (&Y)[8], const float* csl,
                                        unsigned lane, int wb, u64* buf, int tid, int ptid) {
    const float c  = csl[2 * K];
    const float s  = csl[2 * K + 1];
    constexpr int A = G_PA[K], Bp = G_PB[K];
    if constexpr (G_TYPE[K] == 0) {
        if constexpr (A == 9)      ry_warp(X, Y, c, s, buf, tid, ptid, wb);
        else if constexpr (A == 8) ry_pack(X, Y, c, s);
        else if constexpr (A >= 5) ry_reg<A - 5>(X, Y, c, s);
        else                       ry_lane<A>(X, Y, c, s, lane);
    } else {
        if constexpr (A == 9) {            // warp-bit control: free on wb==1
            if (wb) rx_local<Bp>(X, Y, c, s);
        } else if constexpr (Bp == 9) {    // warp-bit target: exchange
            crx_warp_tgt<A>(X, Y, c, s, lane, buf, tid, ptid);
        } else {
            crx_gate<A, Bp>(X, Y, c, s, lane);
        }
    }
}

template<int K = 0>
__device__ __forceinline__ void run_gates(u64 (&X)[8], u64 (&Y)[8], const float* csl,
                                          unsigned lane, int wb, u64* buf, int tid, int ptid) {
    if constexpr (K < 40) {
        do_gate<K>(X, Y, csl, lane, wb, buf, tid, ptid);
        run_gates<K + 1>(X, Y, csl, lane, wb, buf, tid, ptid);
    }
}

// ---- measurement of one wire (x, y, z) from float2 state s[r], amp = r*32+lane
template<int WIRE>
__device__ __forceinline__ void measure_wire(const float2 (&s)[32], unsigned lane, float* outb) {
    constexpr int P = 9 - WIRE;
    float cr = 0.f, ci = 0.f, zz = 0.f;
    if constexpr (P < 5) {
        const int bit = (lane >> P) & 1u;
        const float f0 = bit ? 0.f : 1.f;
        const float zs = bit ? -1.f : 1.f;
#pragma unroll
        for (int r = 0; r < 32; ++r) {
            float px = __shfl_xor_sync(0xffffffffu, s[r].x, 1 << P);
            float py = __shfl_xor_sync(0xffffffffu, s[r].y, 1 << P);
            cr += f0 * (s[r].x * px + s[r].y * py);
            ci += f0 * (s[r].x * py - s[r].y * px);
            zz += zs * (s[r].x * s[r].x + s[r].y * s[r].y);
        }
    } else {
        constexpr int RB = P - 5;
#pragma unroll
        for (int r0 = 0; r0 < 32; ++r0) {
            if ((r0 >> RB) & 1) continue;
            const int r1 = r0 | (1 << RB);
            float2 a0 = s[r0], a1 = s[r1];
            cr += a0.x * a1.x + a0.y * a1.y;
            ci += a0.x * a1.y - a0.y * a1.x;
            zz += (a0.x * a0.x + a0.y * a0.y) - (a1.x * a1.x + a1.y * a1.y);
        }
    }
#pragma unroll
    for (int m = 16; m; m >>= 1) {
        cr += __shfl_xor_sync(0xffffffffu, cr, m);
        ci += __shfl_xor_sync(0xffffffffu, ci, m);
        zz += __shfl_xor_sync(0xffffffffu, zz, m);
    }
    if (lane == 0) {
        outb[WIRE]      = 2.0f * cr;
        outb[10 + WIRE] = 2.0f * ci;
        outb[20 + WIRE] = zz;
    }
}

// ---------------------------------------------------------------------------
// smem layout (bytes):
//   [0, 10240)            cs_s   : 32*40*2 floats
//   [10240, 10560)        ffcs   : 80 floats
//   [10560, 10816)        lcu_s  : 32 float2
//   [10816, 10944)        rsum   : 32 floats
//   [10944, ...)          UNION:
//     phase1: emb_s 32*513 f (65664 B) | W_s 40*512 f (81920 B)
//     phase2: buf/red 16384 u64 (131072 B) | cur 1024 u64 (8192 B)
// ---------------------------------------------------------------------------
#define OFF_UNION  10944
#define TOT_SMEM   (OFF_UNION + 147584)

__global__ void __launch_bounds__(NTHR, 1)
quixer_kernel(const float* __restrict__ emb, const float* __restrict__ W,
              const float* __restrict__ bias,
              const float* __restrict__ lcu_re, const float* __restrict__ lcu_im,
              const float* __restrict__ qsvt, const float* __restrict__ ffp,
              float* __restrict__ out) {
    extern __shared__ char smraw[];
    float*  cs_s  = (float*)smraw;                       // 2560 f
    float*  ffcs  = cs_s + 2560;                         // 80 f
    float2* lcu_s = (float2*)(ffcs + 80);                // 32 f2
    float*  rsum  = (float*)(lcu_s + 32);                // 32 f
    char*   un    = smraw + OFF_UNION;
    float*  emb_s = (float*)un;                          // 32*513
    float*  W_s   = emb_s + 32 * 513;                    // 40*512
    u64*    buf   = (u64*)un;                            // 16*1024 u64 (also red)
    u64*    cur   = buf + 16 * 1024;                     // 1024 u64

    const int b   = blockIdx.x;
    const int tid = threadIdx.x;
    const int w   = tid >> 5;
    const unsigned lane = tid & 31u;
    const int wb   = w & 1;
    const int pair = w >> 1;
    const int ptid = tid ^ 32;

    // ---------------- phase 1: parameter GEMM + trig ----------------
    for (int i = tid; i < 32 * 512; i += NTHR) {
        int l = i >> 9, d = i & 511;
        emb_s[l * 513 + d] = emb[(b * 32 + l) * 512 + d];
    }
    for (int i = tid; i < 40 * 512; i += NTHR) W_s[i] = W[i];

    // ff gate trig + lcu normalization (no dependence on emb/W)
    if (tid < 40) {
        float sv, cv;
        __sincosf(0.5f * ffp[tid], &sv, &cv);
        ffcs[2 * tid] = cv;
        ffcs[2 * tid + 1] = sv;
    }
    if (w == 1) {
        float re = lcu_re[lane], im = lcu_im[lane];
        float S = sqrtf(re * re + im * im);
#pragma unroll
        for (int m = 16; m; m >>= 1) S += __shfl_xor_sync(0xffffffffu, S, m);
        lcu_s[lane] = make_float2(re / S, im / S);
    }
    __syncthreads();

    // dot products: thread -> (l = t&31, k = t>>5); second round covers k 32..39
    {
        const int l0 = tid & 31;
        int k0 = tid >> 5;
        for (int rep = 0; rep < 2; ++rep) {
            if (k0 < 40) {
                const float* er = emb_s + l0 * 513;
                const float* wr = W_s + k0 * 512;
                float acc = 0.f;
#pragma unroll 8
                for (int d = 0; d < 512; ++d) acc = fmaf(er[d], wr[d], acc);
                float th = 0.5f * (acc + bias[k0]);
                float sv, cv;
                __sincosf(th, &sv, &cv);
                cs_s[l0 * 80 + 2 * k0]     = cv;
                cs_s[l0 * 80 + 2 * k0 + 1] = sv;
            }
            k0 += 32;
        }
    }
    __syncthreads();

    // ---------------- phase 2: QSVT mainloop ----------------
    // init |0> : slot tid ; amp0 is (wb=0, X, v=0, lane=0, pack lo)
    cur[tid] = (tid == 0) ? F2(make_float2(1.f, 0.f)) : 0ull;

    const float q0 = qsvt[0], q1 = qsvt[1], q2 = qsvt[2];
    u64 acc = (tid == 0) ? F2(make_float2(q0, 0.f)) : 0ull;
    __syncthreads();

    u64 X[8], Y[8];
    const int wbp = tid >> 9;          // summed-slot half
    const int r   = tid & 511;         // summed-slot offset

    for (int step = 1; step <= 2; ++step) {
        const float qk = (step == 1) ? q1 : q2;
        u64 m = 0ull;
        for (int pass = 0; pass < 2; ++pass) {
            const int l = pair + pass * 16;
            // load half-state
#pragma unroll
            for (int v = 0; v < 8; ++v) {
                X[v] = cur[wb * 512 + v * 32 + lane];
                Y[v] = cur[wb * 512 + 256 + v * 32 + lane];
            }
            // 40 gates
            run_gates(X, Y, cs_s + l * 80, lane, wb, buf, tid, ptid);
            // complex LCU scale
            const float2 lw = lcu_s[l];
            const u64 av = F2(make_float2(lw.x, lw.x));
            const u64 bp = F2(make_float2(lw.y, lw.y));
            const u64 bn = F2(make_float2(-lw.y, -lw.y));
#pragma unroll
            for (int v = 0; v < 8; ++v) {
                u64 tx = X[v];
                X[v] = fma2(bn, Y[v], mul2(av, tx));
                Y[v] = fma2(bp, tx, mul2(av, Y[v]));
            }
            // stage to red (= buf)
            u64* rw = buf + w * 512;
#pragma unroll
            for (int v = 0; v < 8; ++v) {
                rw[v * 32 + lane]       = X[v];
                rw[256 + v * 32 + lane] = Y[v];
            }
            __syncthreads();
            // flat 16-way sum over pairs; thread owns slot (wbp, r)
            u64 a = buf[wbp * 512 + r];
#pragma unroll
            for (int p = 1; p < 16; ++p) a = add2(a, buf[(2 * p + wbp) * 512 + r]);
            m = (pass == 0) ? a : add2(m, a);
            __syncthreads();   // red reuse next pass
        }
        const u64 qk2 = F2(make_float2(qk, qk));
        acc = fma2(qk2, m, acc);
        cur[tid] = m;
        __syncthreads();
    }

    // normalize acc
    {
        float2 t0 = U2(acc);
        float p = t0.x * t0.x + t0.y * t0.y;
#pragma unroll
        for (int mm = 16; mm; mm >>= 1) p += __shfl_xor_sync(0xffffffffu, p, mm);
        if (lane == 0) rsum[w] = p;
    }
    __syncthreads();
    if (tid == 0) {
        float t = 0.f;
#pragma unroll
        for (int i = 0; i < 32; ++i) t += rsum[i];
        rsum[0] = rsqrtf(t);
    }
    __syncthreads();
    {
        const float inv = rsum[0];
        cur[tid] = mul2(acc, F2(make_float2(inv, inv)));
    }
    __syncthreads();

    // feed-forward PQC: all pairs compute redundantly (identical params)
#pragma unroll
    for (int v = 0; v < 8; ++v) {
        X[v] = cur[wb * 512 + v * 32 + lane];
        Y[v] = cur[wb * 512 + 256 + v * 32 + lane];
    }
    run_gates(X, Y, ffcs, lane, wb, buf, tid, ptid);

    // pair 0 writes final state unpacked into fin (reuse buf region)
    float2* fin = (float2*)buf;
    if (w < 2) {
#pragma unroll
        for (int v = 0; v < 8; ++v) {
            float2 xv = U2(X[v]), yv = U2(Y[v]);
            const int r0 = wb * 16 + v;        // pack = 0
            const int r1 = wb * 16 + 8 + v;    // pack = 1
            fin[r0 * 32 + lane] = make_float2(xv.x, yv.x);
            fin[r1 * 32 + lane] = make_float2(xv.y, yv.y);
        }
    }
    __syncthreads();

    // measurement: warps 0..9, one wire each
    if (w < 10) {
        float2 s[32];
#pragma unroll
        for (int rr = 0; rr < 32; ++rr) s[rr] = fin[rr * 32 + lane];
        float* outb = out + b * 30;
        switch (w) {
            case 0: measure_wire<0>(s, lane, outb); break;
            case 1: measure_wire<1>(s, lane, outb); break;
            case 2: measure_wire<2>(s, lane, outb); break;
            case 3: measure_wire<3>(s, lane, outb); break;
            case 4: measure_wire<4>(s, lane, outb); break;
            case 5: measure_wire<5>(s, lane, outb); break;
            case 6: measure_wire<6>(s, lane, outb); break;
            case 7: measure_wire<7>(s, lane, outb); break;
            case 8: measure_wire<8>(s, lane, outb); break;
            case 9: measure_wire<9>(s, lane, outb); break;
        }
    }
}

// ---------------------------------------------------------------------------
extern "C" void kernel_launch(void* const* d_in, const int* in_sizes, int n_in,
                              void* d_out, int out_size) {
    const float* emb    = (const float*)d_in[0];
    const float* W      = (const float*)d_in[1];
    const float* bias   = (const float*)d_in[2];
    const float* lcu_re = (const float*)d_in[3];
    const float* lcu_im = (const float*)d_in[4];
    const float* qsvt   = (const float*)d_in[5];
    const float* ffp    = (const float*)d_in[6];
    float* out = (float*)d_out;

    cudaFuncSetAttribute(quixer_kernel, cudaFuncAttributeMaxDynamicSharedMemorySize, TOT_SMEM);
    quixer_kernel<<<NB, NTHR, TOT_SMEM>>>(emb, W, bias, lcu_re, lcu_im, qsvt, ffp, out);
}

// round 5
// speedup vs baseline: 1.1796x; 1.1796x over previous
#include <cuda_runtime.h>
#include <math.h>

#define NL     32
#define NB     128
#define NPQ    40
#define NTHR   1024

typedef unsigned long long u64;

// ---------------------------------------------------------------------------
// scratch: cos/sin of theta/2 per (b, l, gate)
// ---------------------------------------------------------------------------
__device__ float g_cs[NB * NL * NPQ * 2];

// ---------------------------------------------------------------------------
// gate tables.  bit position = 9 - wire.
// type: 0 = RY (PA = bit pos), 1 = CRX (PA = control bit, PB = target bit)
// ---------------------------------------------------------------------------
constexpr int G_TYPE[40] = {0,0,0,0,0,0,0,0,0,0, 1,1,1,1,1,1,1,1,1,1,
                            0,0,0,0,0,0,0,0,0,0, 1,1,1,1,1,1,1,1,1,1};
constexpr int G_PA[40]   = {9,8,7,6,5,4,3,2,1,0, 0,1,2,3,4,5,6,7,8,9,
                            9,8,7,6,5,4,3,2,1,0, 0,9,8,7,6,5,4,3,2,1};
constexpr int G_PB[40]   = {0,0,0,0,0,0,0,0,0,0, 9,0,1,2,3,4,5,6,7,8,
                            0,0,0,0,0,0,0,0,0,0, 1,0,9,8,7,6,5,4,3,2};

// ---------------------------------------------------------------------------
// f32x2 helpers
// ---------------------------------------------------------------------------
__device__ __forceinline__ u64 F2(float2 v) {
    u64 r; asm("mov.b64 %0, {%1,%2};" : "=l"(r) : "f"(v.x), "f"(v.y)); return r;
}
__device__ __forceinline__ float2 U2(u64 v) {
    float2 p; asm("mov.b64 {%0,%1}, %2;" : "=f"(p.x), "=f"(p.y) : "l"(v)); return p;
}
__device__ __forceinline__ u64 fma2(u64 a, u64 b, u64 c) {
    u64 d; asm("fma.rn.f32x2 %0, %1, %2, %3;" : "=l"(d) : "l"(a), "l"(b), "l"(c)); return d;
}
__device__ __forceinline__ u64 mul2(u64 a, u64 b) {
    u64 d; asm("mul.rn.f32x2 %0, %1, %2;" : "=l"(d) : "l"(a), "l"(b)); return d;
}
__device__ __forceinline__ u64 add2(u64 a, u64 b) {
    u64 d; asm("add.rn.f32x2 %0, %1, %2;" : "=l"(d) : "l"(a), "l"(b)); return d;
}
template<int M>
__device__ __forceinline__ u64 shfl2(u64 v) {
    float2 t = U2(v);
    t.x = __shfl_xor_sync(0xffffffffu, t.x, M);
    t.y = __shfl_xor_sync(0xffffffffu, t.y, M);
    return F2(t);
}
__device__ __forceinline__ u64 swap2(u64 v) {
    float2 t = U2(v);
    return F2(make_float2(t.y, t.x));
}
// named barrier over a 4-warp group (128 threads); ids 1..8 (disjoint from bar 0)
__device__ __forceinline__ void pairbar(int id) {
    asm volatile("bar.sync %0, 128;" :: "r"(id) : "memory");
}

// ---------------------------------------------------------------------------
// state: each PAIR of warps (w, w^1) holds one 1024-amp state.
//   amp = (wb<<9) | (pack<<8) | (v<<5) | lane ;  warp holds X[8], Y[8] u64
//   P<5 -> lane (shfl); 5<=P<8 -> v bit; P==8 -> pack (swap2); P==9 -> warp bit
// ---------------------------------------------------------------------------

template<int P>
__device__ __forceinline__ void ry_lane(u64 (&X)[8], u64 (&Y)[8], float c, float s, unsigned lane) {
    const float sg = ((lane >> P) & 1u) ? s : -s;
    const u64 cc = F2(make_float2(c, c)), sg2 = F2(make_float2(sg, sg));
#pragma unroll
    for (int v = 0; v < 8; ++v) {
        X[v] = fma2(sg2, shfl2<(1 << P)>(X[v]), mul2(cc, X[v]));
        Y[v] = fma2(sg2, shfl2<(1 << P)>(Y[v]), mul2(cc, Y[v]));
    }
}
template<int RB>
__device__ __forceinline__ void ry_reg(u64 (&X)[8], u64 (&Y)[8], float c, float s) {
    const u64 cc = F2(make_float2(c, c));
    const u64 sp = F2(make_float2(s, s)), sn = F2(make_float2(-s, -s));
#pragma unroll
    for (int v0 = 0; v0 < 8; ++v0) {
        if (v0 & (1 << RB)) continue;
        const int v1 = v0 | (1 << RB);
        u64 a0x = X[v0], a1x = X[v1], a0y = Y[v0], a1y = Y[v1];
        X[v0] = fma2(sn, a1x, mul2(cc, a0x));
        X[v1] = fma2(sp, a0x, mul2(cc, a1x));
        Y[v0] = fma2(sn, a1y, mul2(cc, a0y));
        Y[v1] = fma2(sp, a0y, mul2(cc, a1y));
    }
}
__device__ __forceinline__ void ry_pack(u64 (&X)[8], u64 (&Y)[8], float c, float s) {
    const u64 cc = F2(make_float2(c, c)), sv = F2(make_float2(-s, s));
#pragma unroll
    for (int v = 0; v < 8; ++v) {
        X[v] = fma2(sv, swap2(X[v]), mul2(cc, X[v]));
        Y[v] = fma2(sv, swap2(Y[v]), mul2(cc, Y[v]));
    }
}
// RY on warp bit: smem exchange within the 4-warp barrier group
__device__ __forceinline__ void ry_warp(u64 (&X)[8], u64 (&Y)[8], float c, float s,
                                        u64* buf, int tid, int ptid, int barid, int wb) {
#pragma unroll
    for (int i = 0; i < 8; ++i) buf[i * NTHR + tid] = X[i];
#pragma unroll
    for (int i = 0; i < 8; ++i) buf[(8 + i) * NTHR + tid] = Y[i];
    pairbar(barid);
    const float sg = wb ? s : -s;
    const u64 sg2 = F2(make_float2(sg, sg)), cc = F2(make_float2(c, c));
#pragma unroll
    for (int i = 0; i < 8; ++i) X[i] = fma2(sg2, buf[i * NTHR + ptid], mul2(cc, X[i]));
#pragma unroll
    for (int i = 0; i < 8; ++i) Y[i] = fma2(sg2, buf[(8 + i) * NTHR + ptid], mul2(cc, Y[i]));
    pairbar(barid);
}

// RX (uncontrolled or warp-controlled locally) on target B != 9
template<int B>
__device__ __forceinline__ void rx_local(u64 (&X)[8], u64 (&Y)[8], float c, float s) {
    const u64 ce2 = F2(make_float2(c, c));
    const u64 se2 = F2(make_float2(s, s)), sn2 = F2(make_float2(-s, -s));
    if constexpr (B < 5) {
#pragma unroll
        for (int v = 0; v < 8; ++v) {
            u64 px = shfl2<(1 << B)>(X[v]);
            u64 py = shfl2<(1 << B)>(Y[v]);
            X[v] = fma2(se2, py, mul2(ce2, X[v]));
            Y[v] = fma2(sn2, px, mul2(ce2, Y[v]));
        }
    } else if constexpr (B < 8) {
        constexpr int TB = 1 << (B - 5);
#pragma unroll
        for (int v0 = 0; v0 < 8; ++v0) {
            if (v0 & TB) continue;
            const int v1 = v0 | TB;
            u64 a0x = X[v0], a0y = Y[v0], a1x = X[v1], a1y = Y[v1];
            X[v0] = fma2(se2, a1y, mul2(ce2, a0x));
            Y[v0] = fma2(sn2, a1x, mul2(ce2, a0y));
            X[v1] = fma2(se2, a0y, mul2(ce2, a1x));
            Y[v1] = fma2(sn2, a0x, mul2(ce2, a1y));
        }
    } else {
#pragma unroll
        for (int v = 0; v < 8; ++v) {
            u64 sx = swap2(X[v]), sy = swap2(Y[v]);
            X[v] = fma2(se2, sy, mul2(ce2, X[v]));
            Y[v] = fma2(sn2, sx, mul2(ce2, Y[v]));
        }
    }
}

// CRX, control A != 9, target B != 9
template<int A, int B>
__device__ __forceinline__ void crx_gate(u64 (&X)[8], u64 (&Y)[8], float c, float s, unsigned lane) {
    float2 cef, sef;
    if constexpr (A < 5) {
        const int cb = (lane >> A) & 1u;
        const float ce = cb ? c : 1.0f, se = cb ? s : 0.0f;
        cef = make_float2(ce, ce); sef = make_float2(se, se);
    } else if constexpr (A == 8) {
        cef = make_float2(1.0f, c); sef = make_float2(0.0f, s);
    } else {
        cef = make_float2(c, c); sef = make_float2(s, s);
    }
    const u64 ce2 = F2(cef), se2 = F2(sef), sn2 = F2(make_float2(-sef.x, -sef.y));
    constexpr bool vctrl = (A >= 5 && A < 8);
    constexpr int CB = vctrl ? (1 << (A - 5)) : 0;

    if constexpr (B < 5) {
#pragma unroll
        for (int v = 0; v < 8; ++v) {
            if (vctrl && !(v & CB)) continue;
            u64 px = shfl2<(1 << B)>(X[v]);
            u64 py = shfl2<(1 << B)>(Y[v]);
            X[v] = fma2(se2, py, mul2(ce2, X[v]));
            Y[v] = fma2(sn2, px, mul2(ce2, Y[v]));
        }
    } else if constexpr (B < 8) {
        constexpr int TB = 1 << (B - 5);
#pragma unroll
        for (int v0 = 0; v0 < 8; ++v0) {
            if (v0 & TB) continue;
            if (vctrl && !(v0 & CB)) continue;
            const int v1 = v0 | TB;
            u64 a0x = X[v0], a0y = Y[v0], a1x = X[v1], a1y = Y[v1];
            X[v0] = fma2(se2, a1y, mul2(ce2, a0x));
            Y[v0] = fma2(sn2, a1x, mul2(ce2, a0y));
            X[v1] = fma2(se2, a0y, mul2(ce2, a1x));
            Y[v1] = fma2(sn2, a0x, mul2(ce2, a1y));
        }
    } else {
#pragma unroll
        for (int v = 0; v < 8; ++v) {
            if (vctrl && !(v & CB)) continue;
            u64 sx = swap2(X[v]), sy = swap2(Y[v]);
            X[v] = fma2(se2, sy, mul2(ce2, X[v]));
            Y[v] = fma2(sn2, sx, mul2(ce2, Y[v]));
        }
    }
}

// CRX with target = warp bit: smem exchange, coeffs by control A (A==0 or A==8 here)
template<int A>
__device__ __forceinline__ void crx_warp_tgt(u64 (&X)[8], u64 (&Y)[8], float c, float s,
                                             unsigned lane, u64* buf, int tid, int ptid, int barid) {
    float2 cef, sef;
    if constexpr (A < 5) {
        const int cb = (lane >> A) & 1u;
        const float ce = cb ? c : 1.0f, se = cb ? s : 0.0f;
        cef = make_float2(ce, ce); sef = make_float2(se, se);
    } else if constexpr (A == 8) {
        cef = make_float2(1.0f, c); sef = make_float2(0.0f, s);
    } else {
        cef = make_float2(c, c); sef = make_float2(s, s);
    }
    const u64 ce2 = F2(cef), se2 = F2(sef), sn2 = F2(make_float2(-sef.x, -sef.y));
#pragma unroll
    for (int i = 0; i < 8; ++i) buf[i * NTHR + tid] = X[i];
#pragma unroll
    for (int i = 0; i < 8; ++i) buf[(8 + i) * NTHR + tid] = Y[i];
    pairbar(barid);
#pragma unroll
    for (int i = 0; i < 8; ++i) {
        u64 px = buf[i * NTHR + ptid];
        u64 py = buf[(8 + i) * NTHR + ptid];
        X[i] = fma2(se2, py, mul2(ce2, X[i]));
        Y[i] = fma2(sn2, px, mul2(ce2, Y[i]));
    }
    pairbar(barid);
}

template<int K>
__device__ __forceinline__ void do_gate(u64 (&X)[8], u64 (&Y)[8], const float* csl,
                                        unsigned lane, int wb, u64* buf, int tid, int ptid, int barid) {
    const float c = csl[2 * K];
    const float s = csl[2 * K + 1];
    constexpr int A = G_PA[K], Bp = G_PB[K];
    if constexpr (G_TYPE[K] == 0) {
        if constexpr (A == 9)      ry_warp(X, Y, c, s, buf, tid, ptid, barid, wb);
        else if constexpr (A == 8) ry_pack(X, Y, c, s);
        else if constexpr (A >= 5) ry_reg<A - 5>(X, Y, c, s);
        else                       ry_lane<A>(X, Y, c, s, lane);
    } else {
        if constexpr (A == 9) {            // warp-bit control: active only on wb==1
            if (wb) rx_local<Bp>(X, Y, c, s);
        } else if constexpr (Bp == 9) {    // warp-bit target: exchange
            crx_warp_tgt<A>(X, Y, c, s, lane, buf, tid, ptid, barid);
        } else {
            crx_gate<A, Bp>(X, Y, c, s, lane);
        }
    }
}

template<int K = 0>
__device__ __forceinline__ void run_gates(u64 (&X)[8], u64 (&Y)[8], const float* csl,
                                          unsigned lane, int wb, u64* buf, int tid, int ptid, int barid) {
    if constexpr (K < 40) {
        do_gate<K>(X, Y, csl, lane, wb, buf, tid, ptid, barid);
        run_gates<K + 1>(X, Y, csl, lane, wb, buf, tid, ptid, barid);
    }
}

// ---- measurement, streaming from smem (no big register arrays) ----
template<int WIRE>
__device__ __forceinline__ void measure_wire_sm(const float2* fin, unsigned lane, float* outb) {
    constexpr int P = 9 - WIRE;
    float cr = 0.f, ci = 0.f, zz = 0.f;
    if constexpr (P < 5) {
        const int bit = (lane >> P) & 1u;
        const float f0 = bit ? 0.f : 1.f;
        const float zs = bit ? -1.f : 1.f;
#pragma unroll
        for (int r = 0; r < 32; ++r) {
            float2 a = fin[r * 32 + lane];
            float px = __shfl_xor_sync(0xffffffffu, a.x, 1 << P);
            float py = __shfl_xor_sync(0xffffffffu, a.y, 1 << P);
            cr += f0 * (a.x * px + a.y * py);
            ci += f0 * (a.x * py - a.y * px);
            zz += zs * (a.x * a.x + a.y * a.y);
        }
    } else {
        constexpr int RB = P - 5;
#pragma unroll
        for (int r0 = 0; r0 < 32; ++r0) {
            if ((r0 >> RB) & 1) continue;
            float2 a0 = fin[r0 * 32 + lane];
            float2 a1 = fin[(r0 | (1 << RB)) * 32 + lane];
            cr += a0.x * a1.x + a0.y * a1.y;
            ci += a0.x * a1.y - a0.y * a1.x;
            zz += (a0.x * a0.x + a0.y * a0.y) - (a1.x * a1.x + a1.y * a1.y);
        }
    }
#pragma unroll
    for (int m = 16; m; m >>= 1) {
        cr += __shfl_xor_sync(0xffffffffu, cr, m);
        ci += __shfl_xor_sync(0xffffffffu, ci, m);
        zz += __shfl_xor_sync(0xffffffffu, zz, m);
    }
    if (lane == 0) {
        outb[WIRE]      = 2.0f * cr;
        outb[10 + WIRE] = 2.0f * ci;
        outb[20 + WIRE] = zz;
    }
}

// ---------------------------------------------------------------------------
// prep kernel: pqc_params = emb @ W^T + b ; store cos/sin(theta/2)
// ---------------------------------------------------------------------------
#define PREP_SMEM ((32 * 513 + 40 * 512) * 4)

__global__ void __launch_bounds__(256, 1)
prep_kernel(const float* __restrict__ emb, const float* __restrict__ W,
            const float* __restrict__ bias) {
    extern __shared__ float sm[];
    float* emb_s = sm;               // 32 x 513 (padded)
    float* W_s   = sm + 32 * 513;    // 40 x 512
    const int b = blockIdx.x, tid = threadIdx.x;

    for (int i = tid; i < 32 * 512; i += 256) {
        int l = i >> 9, d = i & 511;
        emb_s[l * 513 + d] = emb[(b * 32 + l) * 512 + d];
    }
    for (int i = tid; i < 40 * 512; i += 256) W_s[i] = W[i];
    __syncthreads();

    const int l  = tid & 31;
    const int kg = tid >> 5;             // 0..7, each handles 5 k's
    float acc[5] = {0.f, 0.f, 0.f, 0.f, 0.f};
    const float* er = emb_s + l * 513;
    const float* wr = W_s + kg * 5 * 512;
#pragma unroll 4
    for (int d = 0; d < 512; ++d) {
        float a = er[d];
#pragma unroll
        for (int j = 0; j < 5; ++j) acc[j] += wr[j * 512 + d] * a;
    }
#pragma unroll
    for (int j = 0; j < 5; ++j) {
        int k = kg * 5 + j;
        float th = 0.5f * (acc[j] + bias[k]);
        float sv, cv;
        __sincosf(th, &sv, &cv);
        int base = ((b * 32 + l) * 40 + k) * 2;
        g_cs[base]     = cv;
        g_cs[base + 1] = sv;
    }
}

// ---------------------------------------------------------------------------
// main kernel: one CTA per batch b, 1024 threads (32 warps = 16 pairs)
// smem: buf 16K u64 (128KB) | cur 1024 u64 (8KB) | cs 2560f | ffcs 80f | lcu 32f2 | rsum 32f
// ---------------------------------------------------------------------------
#define MAIN_SMEM (16 * 1024 * 8 + 1024 * 8 + 2560 * 4 + 80 * 4 + 32 * 8 + 32 * 4)

__global__ void __launch_bounds__(NTHR, 1)
main_kernel(const float* __restrict__ lcu_re, const float* __restrict__ lcu_im,
            const float* __restrict__ qsvt, const float* __restrict__ ffp,
            float* __restrict__ out) {
    extern __shared__ char smraw[];
    u64*    buf   = (u64*)smraw;                 // 16*1024 u64 (exchange + reduce)
    u64*    cur   = buf + 16 * 1024;             // 1024 u64  (state; later fin)
    float*  cs_s  = (float*)(cur + 1024);        // 2560 f
    float*  ffcs  = cs_s + 2560;                 // 80 f
    float2* lcu_s = (float2*)(ffcs + 80);        // 32 f2
    float*  rsum  = (float*)(lcu_s + 32);        // 32 f

    const int b   = blockIdx.x;
    const int tid = threadIdx.x;
    const int w   = tid >> 5;
    const unsigned lane = tid & 31u;
    const int wb    = w & 1;
    const int pair  = w >> 1;
    const int ptid  = tid ^ 32;
    const int barid = 1 + (w >> 2);     // 4-warp groups -> ids 1..8

    // stage cos/sin table
    const float* gbase = g_cs + b * (NL * NPQ * 2);
    for (int i = tid; i < NL * NPQ * 2; i += NTHR) cs_s[i] = gbase[i];

    if (tid < 40) {
        float sv, cv;
        __sincosf(0.5f * ffp[tid], &sv, &cv);
        ffcs[2 * tid] = cv;
        ffcs[2 * tid + 1] = sv;
    }
    if (w == 1) {
        float re = lcu_re[lane], im = lcu_im[lane];
        float S = sqrtf(re * re + im * im);
#pragma unroll
        for (int m = 16; m; m >>= 1) S += __shfl_xor_sync(0xffffffffu, S, m);
        lcu_s[lane] = make_float2(re / S, im / S);
    }

    cur[tid] = (tid == 0) ? F2(make_float2(1.f, 0.f)) : 0ull;
    const float q0 = qsvt[0], q1 = qsvt[1], q2 = qsvt[2];
    u64 acc = (tid == 0) ? F2(make_float2(q0, 0.f)) : 0ull;
    __syncthreads();

    u64 X[8], Y[8];
    const int wbp = tid >> 9;
    const int r   = tid & 511;

    for (int step = 1; step <= 2; ++step) {
        const float qk = (step == 1) ? q1 : q2;
        u64 m = 0ull;
        for (int pass = 0; pass < 2; ++pass) {
            const int l = pair + pass * 16;
#pragma unroll
            for (int v = 0; v < 8; ++v) {
                X[v] = cur[wb * 512 + v * 32 + lane];
                Y[v] = cur[wb * 512 + 256 + v * 32 + lane];
            }
            run_gates(X, Y, cs_s + l * 80, lane, wb, buf, tid, ptid, barid);
            // complex LCU scale
            const float2 lw = lcu_s[l];
            const u64 av = F2(make_float2(lw.x, lw.x));
            const u64 bp = F2(make_float2(lw.y, lw.y));
            const u64 bn = F2(make_float2(-lw.y, -lw.y));
#pragma unroll
            for (int v = 0; v < 8; ++v) {
                u64 tx = X[v];
                X[v] = fma2(bn, Y[v], mul2(av, tx));
                Y[v] = fma2(bp, tx, mul2(av, Y[v]));
            }
            __syncthreads();                 // all exchanges done before buf reuse
            // stage to buf for reduction
            u64* rw = buf + w * 512;
#pragma unroll
            for (int v = 0; v < 8; ++v) {
                rw[v * 32 + lane]       = X[v];
                rw[256 + v * 32 + lane] = Y[v];
            }
            __syncthreads();
            // flat 16-way sum over pairs; 2 accumulators for ILP
            u64 a0 = buf[wbp * 512 + r];
            u64 a1 = buf[(2 + wbp) * 512 + r];
#pragma unroll
            for (int p = 2; p < 16; p += 2) {
                a0 = add2(a0, buf[(2 * p + wbp) * 512 + r]);
                a1 = add2(a1, buf[(2 * p + 2 + wbp) * 512 + r]);
            }
            u64 a = add2(a0, a1);
            m = (pass == 0) ? a : add2(m, a);
            __syncthreads();                 // before next pass's exchanges reuse buf
        }
        const u64 qk2 = F2(make_float2(qk, qk));
        acc = fma2(qk2, m, acc);
        cur[tid] = m;
        __syncthreads();
    }

    // normalize acc
    {
        float2 t0 = U2(acc);
        float p = t0.x * t0.x + t0.y * t0.y;
#pragma unroll
        for (int mm = 16; mm; mm >>= 1) p += __shfl_xor_sync(0xffffffffu, p, mm);
        if (lane == 0) rsum[w] = p;
    }
    __syncthreads();
    if (tid == 0) {
        float t = 0.f;
#pragma unroll
        for (int i = 0; i < 32; ++i) t += rsum[i];
        rsum[0] = rsqrtf(t);
    }
    __syncthreads();
    {
        const float inv = rsum[0];
        cur[tid] = mul2(acc, F2(make_float2(inv, inv)));
    }
    __syncthreads();

    // feed-forward PQC: warps 0-3 only (one full 128-thread barrier group, id 1)
    float2* fin = (float2*)buf;          // final state for measurement
    if (w < 4) {
#pragma unroll
        for (int v = 0; v < 8; ++v) {
            X[v] = cur[wb * 512 + v * 32 + lane];
            Y[v] = cur[wb * 512 + 256 + v * 32 + lane];
        }
        run_gates(X, Y, ffcs, lane, wb, buf, tid, ptid, barid);
        if (w < 2) {
            // stash in registers are done; wait for group (pair1 still reading buf)
        }
    }
    __syncthreads();                     // everyone: exchanges done, buf free
    if (w < 2) {
#pragma unroll
        for (int v = 0; v < 8; ++v) {
            float2 xv = U2(X[v]), yv = U2(Y[v]);
            const int r0 = wb * 16 + v;        // pack 0
            const int r1 = wb * 16 + 8 + v;    // pack 1
            fin[r0 * 32 + lane] = make_float2(xv.x, yv.x);
            fin[r1 * 32 + lane] = make_float2(xv.y, yv.y);
        }
    }
    __syncthreads();

    // measurement: warps 0..9, one wire each, streaming from smem
    if (w < 10) {
        float* outb = out + b * 30;
        switch (w) {
            case 0: measure_wire_sm<0>(fin, lane, outb); break;
            case 1: measure_wire_sm<1>(fin, lane, outb); break;
            case 2: measure_wire_sm<2>(fin, lane, outb); break;
            case 3: measure_wire_sm<3>(fin, lane, outb); break;
            case 4: measure_wire_sm<4>(fin, lane, outb); break;
            case 5: measure_wire_sm<5>(fin, lane, outb); break;
            case 6: measure_wire_sm<6>(fin, lane, outb); break;
            case 7: measure_wire_sm<7>(fin, lane, outb); break;
            case 8: measure_wire_sm<8>(fin, lane, outb); break;
            case 9: measure_wire_sm<9>(fin, lane, outb); break;
        }
    }
}

// ---------------------------------------------------------------------------
extern "C" void kernel_launch(void* const* d_in, const int* in_sizes, int n_in,
                              void* d_out, int out_size) {
    const float* emb    = (const float*)d_in[0];
    const float* W      = (const float*)d_in[1];
    const float* bias   = (const float*)d_in[2];
    const float* lcu_re = (const float*)d_in[3];
    const float* lcu_im = (const float*)d_in[4];
    const float* qsvt   = (const float*)d_in[5];
    const float* ffp    = (const float*)d_in[6];
    float* out = (float*)d_out;

    cudaFuncSetAttribute(prep_kernel, cudaFuncAttributeMaxDynamicSharedMemorySize, PREP_SMEM);
    cudaFuncSetAttribute(main_kernel, cudaFuncAttributeMaxDynamicSharedMemorySize, MAIN_SMEM);

    prep_kernel<<<NB, 256, PREP_SMEM>>>(emb, W, bias);
    main_kernel<<<NB, NTHR, MAIN_SMEM>>>(lcu_re, lcu_im, qsvt, ffp, out);
}

// round 8
// speedup vs baseline: 1.2261x; 1.0395x over previous
#include <cuda_runtime.h>
#include <math.h>

#define NL     32
#define NB     128
#define NPQ    40
#define NTHR   1024
#define GRP    128      // threads per barrier group (4 warps)

typedef unsigned long long u64;

// ---------------------------------------------------------------------------
// gate tables.  bit position = 9 - wire.
// type: 0 = RY (PA = bit pos), 1 = CRX (PA = control bit, PB = target bit)
// ---------------------------------------------------------------------------
constexpr int G_TYPE[40] = {0,0,0,0,0,0,0,0,0,0, 1,1,1,1,1,1,1,1,1,1,
                            0,0,0,0,0,0,0,0,0,0, 1,1,1,1,1,1,1,1,1,1};
constexpr int G_PA[40]   = {9,8,7,6,5,4,3,2,1,0, 0,1,2,3,4,5,6,7,8,9,
                            9,8,7,6,5,4,3,2,1,0, 0,9,8,7,6,5,4,3,2,1};
constexpr int G_PB[40]   = {0,0,0,0,0,0,0,0,0,0, 9,0,1,2,3,4,5,6,7,8,
                            0,0,0,0,0,0,0,0,0,0, 1,0,9,8,7,6,5,4,3,2};

// ---------------------------------------------------------------------------
// f32x2 helpers
// ---------------------------------------------------------------------------
__device__ __forceinline__ u64 F2(float2 v) {
    u64 r; asm("mov.b64 %0, {%1,%2};" : "=l"(r) : "f"(v.x), "f"(v.y)); return r;
}
__device__ __forceinline__ float2 U2(u64 v) {
    float2 p; asm("mov.b64 {%0,%1}, %2;" : "=f"(p.x), "=f"(p.y) : "l"(v)); return p;
}
__device__ __forceinline__ u64 fma2(u64 a, u64 b, u64 c) {
    u64 d; asm("fma.rn.f32x2 %0, %1, %2, %3;" : "=l"(d) : "l"(a), "l"(b), "l"(c)); return d;
}
__device__ __forceinline__ u64 mul2(u64 a, u64 b) {
    u64 d; asm("mul.rn.f32x2 %0, %1, %2;" : "=l"(d) : "l"(a), "l"(b)); return d;
}
__device__ __forceinline__ u64 add2(u64 a, u64 b) {
    u64 d; asm("add.rn.f32x2 %0, %1, %2;" : "=l"(d) : "l"(a), "l"(b)); return d;
}
template<int M>
__device__ __forceinline__ u64 shfl2(u64 v) {
    float2 t = U2(v);
    t.x = __shfl_xor_sync(0xffffffffu, t.x, M);
    t.y = __shfl_xor_sync(0xffffffffu, t.y, M);
    return F2(t);
}
__device__ __forceinline__ u64 swap2(u64 v) {
    float2 t = U2(v);
    return F2(make_float2(t.y, t.x));
}
// named barrier over a 4-warp group (128 threads); ids 1..8 (disjoint from bar 0)
__device__ __forceinline__ void pairbar(int id) {
    asm volatile("bar.sync %0, 128;" :: "r"(id) : "memory");
}

// ---------------------------------------------------------------------------
// state: each PAIR of warps (w, w^1) holds one 1024-amp state.
//   amp = (wb<<9) | (pack<<8) | (v<<5) | lane ;  warp holds X[8], Y[8] u64
//   P<5 -> lane (shfl); 5<=P<8 -> v bit; P==8 -> pack (swap2); P==9 -> warp bit
// Exchange region: per-group 16KB slab, ulonglong2 / float views.
// ---------------------------------------------------------------------------

template<int P>
__device__ __forceinline__ void ry_lane(u64 (&X)[8], u64 (&Y)[8], float c, float s, unsigned lane) {
    const float sg = ((lane >> P) & 1u) ? s : -s;
    const u64 cc = F2(make_float2(c, c)), sg2 = F2(make_float2(sg, sg));
#pragma unroll
    for (int v = 0; v < 8; ++v) {
        X[v] = fma2(sg2, shfl2<(1 << P)>(X[v]), mul2(cc, X[v]));
        Y[v] = fma2(sg2, shfl2<(1 << P)>(Y[v]), mul2(cc, Y[v]));
    }
}
template<int RB>
__device__ __forceinline__ void ry_reg(u64 (&X)[8], u64 (&Y)[8], float c, float s) {
    const u64 cc = F2(make_float2(c, c));
    const u64 sp = F2(make_float2(s, s)), sn = F2(make_float2(-s, -s));
#pragma unroll
    for (int v0 = 0; v0 < 8; ++v0) {
        if (v0 & (1 << RB)) continue;
        const int v1 = v0 | (1 << RB);
        u64 a0x = X[v0], a1x = X[v1], a0y = Y[v0], a1y = Y[v1];
        X[v0] = fma2(sn, a1x, mul2(cc, a0x));
        X[v1] = fma2(sp, a0x, mul2(cc, a1x));
        Y[v0] = fma2(sn, a1y, mul2(cc, a0y));
        Y[v1] = fma2(sp, a0y, mul2(cc, a1y));
    }
}
__device__ __forceinline__ void ry_pack(u64 (&X)[8], u64 (&Y)[8], float c, float s) {
    const u64 cc = F2(make_float2(c, c)), sv = F2(make_float2(-s, s));
#pragma unroll
    for (int v = 0; v < 8; ++v) {
        X[v] = fma2(sv, swap2(X[v]), mul2(cc, X[v]));
        Y[v] = fma2(sv, swap2(Y[v]), mul2(cc, Y[v]));
    }
}
// RY on warp bit: full exchange via 128-bit smem ops in the group slab
__device__ __forceinline__ void ry_warp(u64 (&X)[8], u64 (&Y)[8], float c, float s,
                                        ulonglong2* Eg, int gt, int pgt, int barid, int wb) {
#pragma unroll
    for (int i = 0; i < 4; ++i)
        Eg[i * GRP + gt] = make_ulonglong2(X[2 * i], X[2 * i + 1]);
#pragma unroll
    for (int i = 0; i < 4; ++i)
        Eg[(4 + i) * GRP + gt] = make_ulonglong2(Y[2 * i], Y[2 * i + 1]);
    pairbar(barid);
    const float sg = wb ? s : -s;
    const u64 sg2 = F2(make_float2(sg, sg)), cc = F2(make_float2(c, c));
#pragma unroll
    for (int i = 0; i < 4; ++i) {
        ulonglong2 p = Eg[i * GRP + pgt];
        X[2 * i]     = fma2(sg2, p.x, mul2(cc, X[2 * i]));
        X[2 * i + 1] = fma2(sg2, p.y, mul2(cc, X[2 * i + 1]));
    }
#pragma unroll
    for (int i = 0; i < 4; ++i) {
        ulonglong2 p = Eg[(4 + i) * GRP + pgt];
        Y[2 * i]     = fma2(sg2, p.x, mul2(cc, Y[2 * i]));
        Y[2 * i + 1] = fma2(sg2, p.y, mul2(cc, Y[2 * i + 1]));
    }
    pairbar(barid);
}
// CRX k=10: control = lane bit 0, target = warp bit.  Only odd lanes exchange.
__device__ __forceinline__ void crx10(u64 (&X)[8], u64 (&Y)[8], float c, float s,
                                      unsigned lane, ulonglong2* Eg, int gt, int pgt, int barid) {
    const bool act = (lane & 1u) != 0u;
    if (act) {
#pragma unroll
        for (int i = 0; i < 4; ++i)
            Eg[i * GRP + gt] = make_ulonglong2(X[2 * i], X[2 * i + 1]);
#pragma unroll
        for (int i = 0; i < 4; ++i)
            Eg[(4 + i) * GRP + gt] = make_ulonglong2(Y[2 * i], Y[2 * i + 1]);
    }
    pairbar(barid);
    if (act) {
        const u64 cc = F2(make_float2(c, c));
        const u64 sp = F2(make_float2(s, s)), sn = F2(make_float2(-s, -s));
        // x' = c x + s py ; y' = c y - s px   (p = partner across warp bit)
#pragma unroll
        for (int i = 0; i < 4; ++i) {
            ulonglong2 py = Eg[(4 + i) * GRP + pgt];
            X[2 * i]     = fma2(sp, py.x, mul2(cc, X[2 * i]));
            X[2 * i + 1] = fma2(sp, py.y, mul2(cc, X[2 * i + 1]));
        }
#pragma unroll
        for (int i = 0; i < 4; ++i) {
            ulonglong2 px = Eg[i * GRP + pgt];
            Y[2 * i]     = fma2(sn, px.x, mul2(cc, Y[2 * i]));
            Y[2 * i + 1] = fma2(sn, px.y, mul2(cc, Y[2 * i + 1]));
        }
    }
    pairbar(barid);
}
// CRX k=32: control = pack bit (hi half), target = warp bit.  Exchange hi floats only.
__device__ __forceinline__ void crx32(u64 (&X)[8], u64 (&Y)[8], float c, float s,
                                      float* Fg, int gt, int pgt, int barid) {
#pragma unroll
    for (int i = 0; i < 8; ++i) Fg[i * GRP + gt] = U2(X[i]).y;
#pragma unroll
    for (int i = 0; i < 8; ++i) Fg[(8 + i) * GRP + gt] = U2(Y[i]).y;
    pairbar(barid);
#pragma unroll
    for (int i = 0; i < 8; ++i) {
        float pxh = Fg[i * GRP + pgt];
        float pyh = Fg[(8 + i) * GRP + pgt];
        float2 x = U2(X[i]), y = U2(Y[i]);
        x.y = fmaf(s, pyh, c * x.y);
        y.y = fmaf(-s, pxh, c * y.y);
        X[i] = F2(x); Y[i] = F2(y);
    }
    pairbar(barid);
}

// RX (warp-bit-controlled, executes locally on wb==1) on target B != 9
template<int B>
__device__ __forceinline__ void rx_local(u64 (&X)[8], u64 (&Y)[8], float c, float s) {
    const u64 ce2 = F2(make_float2(c, c));
    const u64 se2 = F2(make_float2(s, s)), sn2 = F2(make_float2(-s, -s));
    if constexpr (B < 5) {
#pragma unroll
        for (int v = 0; v < 8; ++v) {
            u64 px = shfl2<(1 << B)>(X[v]);
            u64 py = shfl2<(1 << B)>(Y[v]);
            X[v] = fma2(se2, py, mul2(ce2, X[v]));
            Y[v] = fma2(sn2, px, mul2(ce2, Y[v]));
        }
    } else if constexpr (B < 8) {
        constexpr int TB = 1 << (B - 5);
#pragma unroll
        for (int v0 = 0; v0 < 8; ++v0) {
            if (v0 & TB) continue;
            const int v1 = v0 | TB;
            u64 a0x = X[v0], a0y = Y[v0], a1x = X[v1], a1y = Y[v1];
            X[v0] = fma2(se2, a1y, mul2(ce2, a0x));
            Y[v0] = fma2(sn2, a1x, mul2(ce2, a0y));
            X[v1] = fma2(se2, a0y, mul2(ce2, a1x));
            Y[v1] = fma2(sn2, a0x, mul2(ce2, a1y));
        }
    } else {
#pragma unroll
        for (int v = 0; v < 8; ++v) {
            u64 sx = swap2(X[v]), sy = swap2(Y[v]);
            X[v] = fma2(se2, sy, mul2(ce2, X[v]));
            Y[v] = fma2(sn2, sx, mul2(ce2, Y[v]));
        }
    }
}

// CRX, control A != 9, target B != 9
template<int A, int B>
__device__ __forceinline__ void crx_gate(u64 (&X)[8], u64 (&Y)[8], float c, float s, unsigned lane) {
    float2 cef, sef;
    if constexpr (A < 5) {
        const int cb = (lane >> A) & 1u;
        const float ce = cb ? c : 1.0f, se = cb ? s : 0.0f;
        cef = make_float2(ce, ce); sef = make_float2(se, se);
    } else if constexpr (A == 8) {
        cef = make_float2(1.0f, c); sef = make_float2(0.0f, s);
    } else {
        cef = make_float2(c, c); sef = make_float2(s, s);
    }
    const u64 ce2 = F2(cef), se2 = F2(sef), sn2 = F2(make_float2(-sef.x, -sef.y));
    constexpr bool vctrl = (A >= 5 && A < 8);
    constexpr int CB = vctrl ? (1 << (A - 5)) : 0;

    if constexpr (B < 5) {
#pragma unroll
        for (int v = 0; v < 8; ++v) {
            if (vctrl && !(v & CB)) continue;
            u64 px = shfl2<(1 << B)>(X[v]);
            u64 py = shfl2<(1 << B)>(Y[v]);
            X[v] = fma2(se2, py, mul2(ce2, X[v]));
            Y[v] = fma2(sn2, px, mul2(ce2, Y[v]));
        }
    } else if constexpr (B < 8) {
        constexpr int TB = 1 << (B - 5);
#pragma unroll
        for (int v0 = 0; v0 < 8; ++v0) {
            if (v0 & TB) continue;
            if (vctrl && !(v0 & CB)) continue;
            const int v1 = v0 | TB;
            u64 a0x = X[v0], a0y = Y[v0], a1x = X[v1], a1y = Y[v1];
            X[v0] = fma2(se2, a1y, mul2(ce2, a0x));
            Y[v0] = fma2(sn2, a1x, mul2(ce2, a0y));
            X[v1] = fma2(se2, a0y, mul2(ce2, a1x));
            Y[v1] = fma2(sn2, a0x, mul2(ce2, a1y));
        }
    } else {
#pragma unroll
        for (int v = 0; v < 8; ++v) {
            if (vctrl && !(v & CB)) continue;
            u64 sx = swap2(X[v]), sy = swap2(Y[v]);
            X[v] = fma2(se2, sy, mul2(ce2, X[v]));
            Y[v] = fma2(sn2, sx, mul2(ce2, Y[v]));
        }
    }
}

template<int K>
__device__ __forceinline__ void do_gate(u64 (&X)[8], u64 (&Y)[8], const float* csl,
                                        unsigned lane, int wb,
                                        ulonglong2* Eg, float* Fg, int gt, int pgt, int barid) {
    const float c = csl[2 * K];
    const float s = csl[2 * K + 1];
    constexpr int A = G_PA[K], Bp = G_PB[K];
    if constexpr (K == 0 || K == 20) {
        ry_warp(X, Y, c, s, Eg, gt, pgt, barid, wb);
    } else if constexpr (K == 10) {
        crx10(X, Y, c, s, lane, Eg, gt, pgt, barid);
    } else if constexpr (K == 32) {
        crx32(X, Y, c, s, Fg, gt, pgt, barid);
    } else if constexpr (G_TYPE[K] == 1 && A == 9) {
        if (wb) rx_local<Bp>(X, Y, c, s);
    } else if constexpr (G_TYPE[K] == 0) {
        if constexpr (A == 8)      ry_pack(X, Y, c, s);
        else if constexpr (A >= 5) ry_reg<A - 5>(X, Y, c, s);
        else                       ry_lane<A>(X, Y, c, s, lane);
    } else {
        crx_gate<A, Bp>(X, Y, c, s, lane);
    }
}

template<int K = 0>
__device__ __forceinline__ void run_gates(u64 (&X)[8], u64 (&Y)[8], const float* csl,
                                          unsigned lane, int wb,
                                          ulonglong2* Eg, float* Fg, int gt, int pgt, int barid) {
    if constexpr (K < 40) {
        do_gate<K>(X, Y, csl, lane, wb, Eg, Fg, gt, pgt, barid);
        run_gates<K + 1>(X, Y, csl, lane, wb, Eg, Fg, gt, pgt, barid);
    }
}

// ---- measurement, streaming from smem ----
template<int WIRE>
__device__ __forceinline__ void measure_wire_sm(const float2* fin, unsigned lane, float* outb) {
    constexpr int P = 9 - WIRE;
    float cr = 0.f, ci = 0.f, zz = 0.f;
    if constexpr (P < 5) {
        const int bit = (lane >> P) & 1u;
        const float f0 = bit ? 0.f : 1.f;
        const float zs = bit ? -1.f : 1.f;
#pragma unroll
        for (int r = 0; r < 32; ++r) {
            float2 a = fin[r * 32 + lane];
            float px = __shfl_xor_sync(0xffffffffu, a.x, 1 << P);
            float py = __shfl_xor_sync(0xffffffffu, a.y, 1 << P);
            cr += f0 * (a.x * px + a.y * py);
            ci += f0 * (a.x * py - a.y * px);
            zz += zs * (a.x * a.x + a.y * a.y);
        }
    } else {
        constexpr int RB = P - 5;
#pragma unroll
        for (int r0 = 0; r0 < 32; ++r0) {
            if ((r0 >> RB) & 1) continue;
            float2 a0 = fin[r0 * 32 + lane];
            float2 a1 = fin[(r0 | (1 << RB)) * 32 + lane];
            cr += a0.x * a1.x + a0.y * a1.y;
            ci += a0.x * a1.y - a0.y * a1.x;
            zz += (a0.x * a0.x + a0.y * a0.y) - (a1.x * a1.x + a1.y * a1.y);
        }
    }
#pragma unroll
    for (int m = 16; m; m >>= 1) {
        cr += __shfl_xor_sync(0xffffffffu, cr, m);
        ci += __shfl_xor_sync(0xffffffffu, ci, m);
        zz += __shfl_xor_sync(0xffffffffu, zz, m);
    }
    if (lane == 0) {
        outb[WIRE]      = 2.0f * cr;
        outb[10 + WIRE] = 2.0f * ci;
        outb[20 + WIRE] = zz;
    }
}

// ---------------------------------------------------------------------------
// smem layout (bytes):
//   [0,10240)      cs_s  2560 f
//   [10240,10560)  ffcs  80 f
//   [10560,10816)  lcu_s 32 f2
//   [10816,10944)  rsum  32 f
//   [10944, ...)   UNION:
//     GEMM:  emb_s 32*513 f (65664) | W_s 40*512 f (81920)   = 147584
//     MAIN:  buf 16384 u64 (131072) | cur 1024 u64 (8192)    = 139264
// ---------------------------------------------------------------------------
#define OFF_UNION  10944
#define TOT_SMEM   (OFF_UNION + 147584)

__global__ void __launch_bounds__(NTHR, 1)
quixer_kernel(const float* __restrict__ emb, const float* __restrict__ W,
              const float* __restrict__ bias,
              const float* __restrict__ lcu_re, const float* __restrict__ lcu_im,
              const float* __restrict__ qsvt, const float* __restrict__ ffp,
              float* __restrict__ out) {
    extern __shared__ char smraw[];
    float*  cs_s  = (float*)smraw;                       // 2560 f
    float*  ffcs  = cs_s + 2560;                         // 80 f
    float2* lcu_s = (float2*)(ffcs + 80);                // 32 f2
    float*  rsum  = (float*)(lcu_s + 32);                // 32 f
    char*   un    = smraw + OFF_UNION;
    float*  emb_s = (float*)un;                          // 32*513
    float*  W_s   = emb_s + 32 * 513;                    // 40*512
    u64*    buf   = (u64*)un;                            // 16*1024 u64
    u64*    cur   = buf + 16 * 1024;                     // 1024 u64

    const int b   = blockIdx.x;
    const int tid = threadIdx.x;
    const int w   = tid >> 5;
    const unsigned lane = tid & 31u;
    const int wb    = w & 1;
    const int pair  = w >> 1;
    const int grp   = w >> 2;                 // 4-warp group 0..7
    const int gt    = tid & (GRP - 1);        // id within group
    const int pgt   = gt ^ 32;                // partner within group
    const int barid = 1 + grp;                // named bars 1..8
    ulonglong2* Eg  = (ulonglong2*)buf + grp * 1024;  // 16KB slab per group
    float*      Fg  = (float*)Eg;

    // ---------------- phase 1: GEMM + trig ----------------
    for (int i = tid; i < 32 * 512; i += NTHR) {
        int l = i >> 9, d = i & 511;
        emb_s[l * 513 + d] = emb[(b * 32 + l) * 512 + d];
    }
    for (int i = tid; i < 40 * 512; i += NTHR) W_s[i] = W[i];

    if (tid < 40) {
        float sv, cv;
        __sincosf(0.5f * ffp[tid], &sv, &cv);
        ffcs[2 * tid] = cv;
        ffcs[2 * tid + 1] = sv;
    }
    if (w == 1) {
        float re = lcu_re[lane], im = lcu_im[lane];
        float S = sqrtf(re * re + im * im);
#pragma unroll
        for (int m = 16; m; m >>= 1) S += __shfl_xor_sync(0xffffffffu, S, m);
        lcu_s[lane] = make_float2(re / S, im / S);
    }
    __syncthreads();

    if (tid < 256) {
        const int l  = tid & 31;
        const int kg = tid >> 5;             // 0..7, each handles 5 k's
        float acc5[5] = {0.f, 0.f, 0.f, 0.f, 0.f};
        const float* er = emb_s + l * 513;
        const float* wr = W_s + kg * 5 * 512;
#pragma unroll 4
        for (int d = 0; d < 512; ++d) {
            float a = er[d];
#pragma unroll
            for (int j = 0; j < 5; ++j) acc5[j] += wr[j * 512 + d] * a;
        }
#pragma unroll
        for (int j = 0; j < 5; ++j) {
            int k = kg * 5 + j;
            float th = 0.5f * (acc5[j] + bias[k]);
            float sv, cv;
            __sincosf(th, &sv, &cv);
            cs_s[l * 80 + 2 * k]     = cv;
            cs_s[l * 80 + 2 * k + 1] = sv;
        }
    }
    __syncthreads();   // cs ready; union region free for buf/cur

    // ---------------- phase 2: QSVT mainloop ----------------
    cur[tid] = (tid == 0) ? F2(make_float2(1.f, 0.f)) : 0ull;
    const float q0 = qsvt[0], q1 = qsvt[1], q2 = qsvt[2];
    u64 acc = (tid == 0) ? F2(make_float2(q0, 0.f)) : 0ull;
    __syncthreads();

    u64 X[8], Y[8];
    const int wbp = tid >> 9;
    const int r   = tid & 511;

    for (int step = 1; step <= 2; ++step) {
        const float qk = (step == 1) ? q1 : q2;
        u64 m = 0ull;
        for (int pass = 0; pass < 2; ++pass) {
            const int l = pair + pass * 16;
#pragma unroll
            for (int v = 0; v < 8; ++v) {
                X[v] = cur[wb * 512 + v * 32 + lane];
                Y[v] = cur[wb * 512 + 256 + v * 32 + lane];
            }
            run_gates(X, Y, cs_s + l * 80, lane, wb, Eg, Fg, gt, pgt, barid);
            // complex LCU scale
            const float2 lw = lcu_s[l];
            const u64 av = F2(make_float2(lw.x, lw.x));
            const u64 bp = F2(make_float2(lw.y, lw.y));
            const u64 bn = F2(make_float2(-lw.y, -lw.y));
#pragma unroll
            for (int v = 0; v < 8; ++v) {
                u64 tx = X[v];
                X[v] = fma2(bn, Y[v], mul2(av, tx));
                Y[v] = fma2(bp, tx, mul2(av, Y[v]));
            }
            __syncthreads();                 // exchanges done before buf reuse
            u64* rw = buf + w * 512;
#pragma unroll
            for (int v = 0; v < 8; ++v) {
                rw[v * 32 + lane]       = X[v];
                rw[256 + v * 32 + lane] = Y[v];
            }
            __syncthreads();
            // flat 16-way sum over pairs; 2 accumulators for ILP
            u64 a0 = buf[wbp * 512 + r];
            u64 a1 = buf[(2 + wbp) * 512 + r];
#pragma unroll
            for (int p = 2; p < 16; p += 2) {
                a0 = add2(a0, buf[(2 * p + wbp) * 512 + r]);
                a1 = add2(a1, buf[(2 * p + 2 + wbp) * 512 + r]);
            }
            u64 a = add2(a0, a1);
            m = (pass == 0) ? a : add2(m, a);
            __syncthreads();                 // before next pass reuses buf
        }
        const u64 qk2 = F2(make_float2(qk, qk));
        acc = fma2(qk2, m, acc);
        if (step == 1) {
            cur[tid] = m;
            __syncthreads();
        }
    }

    // normalize acc
    {
        float2 t0 = U2(acc);
        float p = t0.x * t0.x + t0.y * t0.y;
#pragma unroll
        for (int mm = 16; mm; mm >>= 1) p += __shfl_xor_sync(0xffffffffu, p, mm);
        if (lane == 0) rsum[w] = p;
    }
    __syncthreads();
    if (tid == 0) {
        float t = 0.f;
#pragma unroll
        for (int i = 0; i < 32; ++i) t += rsum[i];
        rsum[0] = rsqrtf(t);
    }
    __syncthreads();
    {
        const float inv = rsum[0];
        cur[tid] = mul2(acc, F2(make_float2(inv, inv)));
    }
    __syncthreads();

    // feed-forward PQC: warps 0-3 only (group 0, barid 1)
    float2* fin = (float2*)buf;
    if (w < 4) {
#pragma unroll
        for (int v = 0; v < 8; ++v) {
            X[v] = cur[wb * 512 + v * 32 + lane];
            Y[v] = cur[wb * 512 + 256 + v * 32 + lane];
        }
        run_gates(X, Y, ffcs, lane, wb, Eg, Fg, gt, pgt, barid);
    }
    __syncthreads();                     // exchanges done, buf free
    if (w < 2) {
#pragma unroll
        for (int v = 0; v < 8; ++v) {
            float2 xv = U2(X[v]), yv = U2(Y[v]);
            const int r0 = wb * 16 + v;        // pack 0
            const int r1 = wb * 16 + 8 + v;    // pack 1
            fin[r0 * 32 + lane] = make_float2(xv.x, yv.x);
            fin[r1 * 32 + lane] = make_float2(xv.y, yv.y);
        }
    }
    __syncthreads();

    // measurement: warps 0..9, one wire each
    if (w < 10) {
        float* outb = out + b * 30;
        switch (w) {
            case 0: measure_wire_sm<0>(fin, lane, outb); break;
            case 1: measure_wire_sm<1>(fin, lane, outb); break;
            case 2: measure_wire_sm<2>(fin, lane, outb); break;
            case 3: measure_wire_sm<3>(fin, lane, outb); break;
            case 4: measure_wire_sm<4>(fin, lane, outb); break;
            case 5: measure_wire_sm<5>(fin, lane, outb); break;
            case 6: measure_wire_sm<6>(fin, lane, outb); break;
            case 7: measure_wire_sm<7>(fin, lane, outb); break;
            case 8: measure_wire_sm<8>(fin, lane, outb); break;
            case 9: measure_wire_sm<9>(fin, lane, outb); break;
        }
    }
}

// ---------------------------------------------------------------------------
extern "C" void kernel_launch(void* const* d_in, const int* in_sizes, int n_in,
                              void* d_out, int out_size) {
    const float* emb    = (const float*)d_in[0];
    const float* W      = (const float*)d_in[1];
    const float* bias   = (const float*)d_in[2];
    const float* lcu_re = (const float*)d_in[3];
    const float* lcu_im = (const float*)d_in[4];
    const float* qsvt   = (const float*)d_in[5];
    const float* ffp    = (const float*)d_in[6];
    float* out = (float*)d_out;

    cudaFuncSetAttribute(quixer_kernel, cudaFuncAttributeMaxDynamicSharedMemorySize, TOT_SMEM);
    quixer_kernel<<<NB, NTHR, TOT_SMEM>>>(emb, W, bias, lcu_re, lcu_im, qsvt, ffp, out);
}

// round 9
// speedup vs baseline: 1.3255x; 1.0810x over previous
#include <cuda_runtime.h>
#include <math.h>

#define NL     32
#define NB     128
#define NPQ    40
#define NTHR   1024
#define GRP    128      // threads per barrier group (4 warps)

typedef unsigned long long u64;

// ---------------------------------------------------------------------------
// gate tables.  bit position = 9 - wire.
// type: 0 = RY (PA = bit pos), 1 = CRX (PA = control bit, PB = target bit)
// ---------------------------------------------------------------------------
constexpr int G_TYPE[40] = {0,0,0,0,0,0,0,0,0,0, 1,1,1,1,1,1,1,1,1,1,
                            0,0,0,0,0,0,0,0,0,0, 1,1,1,1,1,1,1,1,1,1};
constexpr int G_PA[40]   = {9,8,7,6,5,4,3,2,1,0, 0,1,2,3,4,5,6,7,8,9,
                            9,8,7,6,5,4,3,2,1,0, 0,9,8,7,6,5,4,3,2,1};
constexpr int G_PB[40]   = {0,0,0,0,0,0,0,0,0,0, 9,0,1,2,3,4,5,6,7,8,
                            0,0,0,0,0,0,0,0,0,0, 1,0,9,8,7,6,5,4,3,2};

// ---------------------------------------------------------------------------
// f32x2 helpers
// ---------------------------------------------------------------------------
__device__ __forceinline__ u64 F2(float2 v) {
    u64 r; asm("mov.b64 %0, {%1,%2};" : "=l"(r) : "f"(v.x), "f"(v.y)); return r;
}
__device__ __forceinline__ float2 U2(u64 v) {
    float2 p; asm("mov.b64 {%0,%1}, %2;" : "=f"(p.x), "=f"(p.y) : "l"(v)); return p;
}
__device__ __forceinline__ u64 fma2(u64 a, u64 b, u64 c) {
    u64 d; asm("fma.rn.f32x2 %0, %1, %2, %3;" : "=l"(d) : "l"(a), "l"(b), "l"(c)); return d;
}
__device__ __forceinline__ u64 mul2(u64 a, u64 b) {
    u64 d; asm("mul.rn.f32x2 %0, %1, %2;" : "=l"(d) : "l"(a), "l"(b)); return d;
}
__device__ __forceinline__ u64 add2(u64 a, u64 b) {
    u64 d; asm("add.rn.f32x2 %0, %1, %2;" : "=l"(d) : "l"(a), "l"(b)); return d;
}
template<int M>
__device__ __forceinline__ u64 shfl2(u64 v) {
    float2 t = U2(v);
    t.x = __shfl_xor_sync(0xffffffffu, t.x, M);
    t.y = __shfl_xor_sync(0xffffffffu, t.y, M);
    return F2(t);
}
__device__ __forceinline__ u64 swap2(u64 v) {
    float2 t = U2(v);
    return F2(make_float2(t.y, t.x));
}
// named barrier over a 4-warp group (128 threads); ids 1..8 (disjoint from bar 0)
__device__ __forceinline__ void pairbar(int id) {
    asm volatile("bar.sync %0, 128;" :: "r"(id) : "memory");
}

// ---------------------------------------------------------------------------
// state: each PAIR of warps (w, w^1) holds one 1024-amp state.
//   amp = (wb<<9) | (pack<<8) | (v<<5) | lane ;  warp holds X[8], Y[8] u64
//   P<5 -> lane (shfl); 5<=P<8 -> v bit; P==8 -> pack (swap2); P==9 -> warp bit
// Exchange region: per-group 16KB slab, ulonglong2 / float views.
// ---------------------------------------------------------------------------

template<int P>
__device__ __forceinline__ void ry_lane(u64 (&X)[8], u64 (&Y)[8], float c, float s, unsigned lane) {
    const float sg = ((lane >> P) & 1u) ? s : -s;
    const u64 cc = F2(make_float2(c, c)), sg2 = F2(make_float2(sg, sg));
#pragma unroll
    for (int v = 0; v < 8; ++v) {
        X[v] = fma2(sg2, shfl2<(1 << P)>(X[v]), mul2(cc, X[v]));
        Y[v] = fma2(sg2, shfl2<(1 << P)>(Y[v]), mul2(cc, Y[v]));
    }
}
template<int RB>
__device__ __forceinline__ void ry_reg(u64 (&X)[8], u64 (&Y)[8], float c, float s) {
    const u64 cc = F2(make_float2(c, c));
    const u64 sp = F2(make_float2(s, s)), sn = F2(make_float2(-s, -s));
#pragma unroll
    for (int v0 = 0; v0 < 8; ++v0) {
        if (v0 & (1 << RB)) continue;
        const int v1 = v0 | (1 << RB);
        u64 a0x = X[v0], a1x = X[v1], a0y = Y[v0], a1y = Y[v1];
        X[v0] = fma2(sn, a1x, mul2(cc, a0x));
        X[v1] = fma2(sp, a0x, mul2(cc, a1x));
        Y[v0] = fma2(sn, a1y, mul2(cc, a0y));
        Y[v1] = fma2(sp, a0y, mul2(cc, a1y));
    }
}
__device__ __forceinline__ void ry_pack(u64 (&X)[8], u64 (&Y)[8], float c, float s) {
    const u64 cc = F2(make_float2(c, c)), sv = F2(make_float2(-s, s));
#pragma unroll
    for (int v = 0; v < 8; ++v) {
        X[v] = fma2(sv, swap2(X[v]), mul2(cc, X[v]));
        Y[v] = fma2(sv, swap2(Y[v]), mul2(cc, Y[v]));
    }
}
// RY on warp bit: full exchange via 128-bit smem ops in the group slab
__device__ __forceinline__ void ry_warp(u64 (&X)[8], u64 (&Y)[8], float c, float s,
                                        ulonglong2* Eg, int gt, int pgt, int barid, int wb) {
#pragma unroll
    for (int i = 0; i < 4; ++i)
        Eg[i * GRP + gt] = make_ulonglong2(X[2 * i], X[2 * i + 1]);
#pragma unroll
    for (int i = 0; i < 4; ++i)
        Eg[(4 + i) * GRP + gt] = make_ulonglong2(Y[2 * i], Y[2 * i + 1]);
    pairbar(barid);
    const float sg = wb ? s : -s;
    const u64 sg2 = F2(make_float2(sg, sg)), cc = F2(make_float2(c, c));
#pragma unroll
    for (int i = 0; i < 4; ++i) {
        ulonglong2 p = Eg[i * GRP + pgt];
        X[2 * i]     = fma2(sg2, p.x, mul2(cc, X[2 * i]));
        X[2 * i + 1] = fma2(sg2, p.y, mul2(cc, X[2 * i + 1]));
    }
#pragma unroll
    for (int i = 0; i < 4; ++i) {
        ulonglong2 p = Eg[(4 + i) * GRP + pgt];
        Y[2 * i]     = fma2(sg2, p.x, mul2(cc, Y[2 * i]));
        Y[2 * i + 1] = fma2(sg2, p.y, mul2(cc, Y[2 * i + 1]));
    }
    pairbar(barid);
}
// CRX k=10: control = lane bit 0, target = warp bit.  Only odd lanes exchange.
__device__ __forceinline__ void crx10(u64 (&X)[8], u64 (&Y)[8], float c, float s,
                                      unsigned lane, ulonglong2* Eg, int gt, int pgt, int barid) {
    const bool act = (lane & 1u) != 0u;
    if (act) {
#pragma unroll
        for (int i = 0; i < 4; ++i)
            Eg[i * GRP + gt] = make_ulonglong2(X[2 * i], X[2 * i + 1]);
#pragma unroll
        for (int i = 0; i < 4; ++i)
            Eg[(4 + i) * GRP + gt] = make_ulonglong2(Y[2 * i], Y[2 * i + 1]);
    }
    pairbar(barid);
    if (act) {
        const u64 cc = F2(make_float2(c, c));
        const u64 sp = F2(make_float2(s, s)), sn = F2(make_float2(-s, -s));
#pragma unroll
        for (int i = 0; i < 4; ++i) {
            ulonglong2 py = Eg[(4 + i) * GRP + pgt];
            X[2 * i]     = fma2(sp, py.x, mul2(cc, X[2 * i]));
            X[2 * i + 1] = fma2(sp, py.y, mul2(cc, X[2 * i + 1]));
        }
#pragma unroll
        for (int i = 0; i < 4; ++i) {
            ulonglong2 px = Eg[i * GRP + pgt];
            Y[2 * i]     = fma2(sn, px.x, mul2(cc, Y[2 * i]));
            Y[2 * i + 1] = fma2(sn, px.y, mul2(cc, Y[2 * i + 1]));
        }
    }
    pairbar(barid);
}
// CRX k=10 with Y==0 everywhere (step-1 fast path): exchange X only.
__device__ __forceinline__ void crx10_y0(u64 (&X)[8], u64 (&Y)[8], float c, float s,
                                         unsigned lane, ulonglong2* Eg, int gt, int pgt, int barid) {
    const bool act = (lane & 1u) != 0u;
    if (act) {
#pragma unroll
        for (int i = 0; i < 4; ++i)
            Eg[i * GRP + gt] = make_ulonglong2(X[2 * i], X[2 * i + 1]);
    }
    pairbar(barid);
    if (act) {
        const u64 cc = F2(make_float2(c, c));
        const u64 sn = F2(make_float2(-s, -s));
#pragma unroll
        for (int i = 0; i < 4; ++i) {
            ulonglong2 px = Eg[i * GRP + pgt];
            Y[2 * i]     = mul2(sn, px.x);       // y' = -s * partner_x   (y was 0)
            Y[2 * i + 1] = mul2(sn, px.y);
            X[2 * i]     = mul2(cc, X[2 * i]);   // x' = c * x (partner_y = 0)
            X[2 * i + 1] = mul2(cc, X[2 * i + 1]);
        }
    }
    pairbar(barid);
}
// CRX k=32: control = pack bit (hi half), target = warp bit.  Exchange hi floats only.
__device__ __forceinline__ void crx32(u64 (&X)[8], u64 (&Y)[8], float c, float s,
                                      float* Fg, int gt, int pgt, int barid) {
#pragma unroll
    for (int i = 0; i < 8; ++i) Fg[i * GRP + gt] = U2(X[i]).y;
#pragma unroll
    for (int i = 0; i < 8; ++i) Fg[(8 + i) * GRP + gt] = U2(Y[i]).y;
    pairbar(barid);
#pragma unroll
    for (int i = 0; i < 8; ++i) {
        float pxh = Fg[i * GRP + pgt];
        float pyh = Fg[(8 + i) * GRP + pgt];
        float2 x = U2(X[i]), y = U2(Y[i]);
        x.y = fmaf(s, pyh, c * x.y);
        y.y = fmaf(-s, pxh, c * y.y);
        X[i] = F2(x); Y[i] = F2(y);
    }
    pairbar(barid);
}

// RX (warp-bit-controlled, executes locally on wb==1) on target B != 9
template<int B>
__device__ __forceinline__ void rx_local(u64 (&X)[8], u64 (&Y)[8], float c, float s) {
    const u64 ce2 = F2(make_float2(c, c));
    const u64 se2 = F2(make_float2(s, s)), sn2 = F2(make_float2(-s, -s));
    if constexpr (B < 5) {
#pragma unroll
        for (int v = 0; v < 8; ++v) {
            u64 px = shfl2<(1 << B)>(X[v]);
            u64 py = shfl2<(1 << B)>(Y[v]);
            X[v] = fma2(se2, py, mul2(ce2, X[v]));
            Y[v] = fma2(sn2, px, mul2(ce2, Y[v]));
        }
    } else if constexpr (B < 8) {
        constexpr int TB = 1 << (B - 5);
#pragma unroll
        for (int v0 = 0; v0 < 8; ++v0) {
            if (v0 & TB) continue;
            const int v1 = v0 | TB;
            u64 a0x = X[v0], a0y = Y[v0], a1x = X[v1], a1y = Y[v1];
            X[v0] = fma2(se2, a1y, mul2(ce2, a0x));
            Y[v0] = fma2(sn2, a1x, mul2(ce2, a0y));
            X[v1] = fma2(se2, a0y, mul2(ce2, a1x));
            Y[v1] = fma2(sn2, a0x, mul2(ce2, a1y));
        }
    } else {
#pragma unroll
        for (int v = 0; v < 8; ++v) {
            u64 sx = swap2(X[v]), sy = swap2(Y[v]);
            X[v] = fma2(se2, sy, mul2(ce2, X[v]));
            Y[v] = fma2(sn2, sx, mul2(ce2, Y[v]));
        }
    }
}

// CRX, control A != 9, target B != 9
template<int A, int B>
__device__ __forceinline__ void crx_gate(u64 (&X)[8], u64 (&Y)[8], float c, float s, unsigned lane) {
    float2 cef, sef;
    if constexpr (A < 5) {
        const int cb = (lane >> A) & 1u;
        const float ce = cb ? c : 1.0f, se = cb ? s : 0.0f;
        cef = make_float2(ce, ce); sef = make_float2(se, se);
    } else if constexpr (A == 8) {
        cef = make_float2(1.0f, c); sef = make_float2(0.0f, s);
    } else {
        cef = make_float2(c, c); sef = make_float2(s, s);
    }
    const u64 ce2 = F2(cef), se2 = F2(sef), sn2 = F2(make_float2(-sef.x, -sef.y));
    constexpr bool vctrl = (A >= 5 && A < 8);
    constexpr int CB = vctrl ? (1 << (A - 5)) : 0;

    if constexpr (B < 5) {
#pragma unroll
        for (int v = 0; v < 8; ++v) {
            if (vctrl && !(v & CB)) continue;
            u64 px = shfl2<(1 << B)>(X[v]);
            u64 py = shfl2<(1 << B)>(Y[v]);
            X[v] = fma2(se2, py, mul2(ce2, X[v]));
            Y[v] = fma2(sn2, px, mul2(ce2, Y[v]));
        }
    } else if constexpr (B < 8) {
        constexpr int TB = 1 << (B - 5);
#pragma unroll
        for (int v0 = 0; v0 < 8; ++v0) {
            if (v0 & TB) continue;
            if (vctrl && !(v0 & CB)) continue;
            const int v1 = v0 | TB;
            u64 a0x = X[v0], a0y = Y[v0], a1x = X[v1], a1y = Y[v1];
            X[v0] = fma2(se2, a1y, mul2(ce2, a0x));
            Y[v0] = fma2(sn2, a1x, mul2(ce2, a0y));
            X[v1] = fma2(se2, a0y, mul2(ce2, a1x));
            Y[v1] = fma2(sn2, a0x, mul2(ce2, a1y));
        }
    } else {
#pragma unroll
        for (int v = 0; v < 8; ++v) {
            if (vctrl && !(v & CB)) continue;
            u64 sx = swap2(X[v]), sy = swap2(Y[v]);
            X[v] = fma2(se2, sy, mul2(ce2, X[v]));
            Y[v] = fma2(sn2, sx, mul2(ce2, Y[v]));
        }
    }
}

template<int K>
__device__ __forceinline__ void do_gate(u64 (&X)[8], u64 (&Y)[8], const float* csl,
                                        unsigned lane, int wb,
                                        ulonglong2* Eg, float* Fg, int gt, int pgt, int barid) {
    const float c = csl[2 * K];
    const float s = csl[2 * K + 1];
    constexpr int A = G_PA[K], Bp = G_PB[K];
    if constexpr (K == 0 || K == 20) {
        ry_warp(X, Y, c, s, Eg, gt, pgt, barid, wb);
    } else if constexpr (K == 10) {
        crx10(X, Y, c, s, lane, Eg, gt, pgt, barid);
    } else if constexpr (K == 32) {
        crx32(X, Y, c, s, Fg, gt, pgt, barid);
    } else if constexpr (G_TYPE[K] == 1 && A == 9) {
        if (wb) rx_local<Bp>(X, Y, c, s);
    } else if constexpr (G_TYPE[K] == 0) {
        if constexpr (A == 8)      ry_pack(X, Y, c, s);
        else if constexpr (A >= 5) ry_reg<A - 5>(X, Y, c, s);
        else                       ry_lane<A>(X, Y, c, s, lane);
    } else {
        crx_gate<A, Bp>(X, Y, c, s, lane);
    }
}

template<int K, int KEND = 40>
__device__ __forceinline__ void run_gates(u64 (&X)[8], u64 (&Y)[8], const float* csl,
                                          unsigned lane, int wb,
                                          ulonglong2* Eg, float* Fg, int gt, int pgt, int barid) {
    if constexpr (K < KEND) {
        do_gate<K>(X, Y, csl, lane, wb, Eg, Fg, gt, pgt, barid);
        run_gates<K + 1, KEND>(X, Y, csl, lane, wb, Eg, Fg, gt, pgt, barid);
    }
}

// ---- step-1 shortcut: product state after the first RY layer (gates 0..9) ----
// amp(idx) = prod over bits P: ((idx>>P)&1 ? sin_k : cos_k), k = 9-P.  Y = 0.
__device__ __forceinline__ void build_ry_product(u64 (&X)[8], u64 (&Y)[8],
                                                 const float* cs, unsigned lane, int wb) {
    float A = wb ? cs[1] : cs[0];                      // P=9, k=0
    A *= (lane & 1u)  ? cs[19] : cs[18];               // P=0, k=9
    A *= (lane & 2u)  ? cs[17] : cs[16];               // P=1, k=8
    A *= (lane & 4u)  ? cs[15] : cs[14];               // P=2, k=7
    A *= (lane & 8u)  ? cs[13] : cs[12];               // P=3, k=6
    A *= (lane & 16u) ? cs[11] : cs[10];               // P=4, k=5
    const float c4 = cs[8],  s4 = cs[9];               // P=5, k=4  (v bit 0)
    const float c3 = cs[6],  s3 = cs[7];               // P=6, k=3  (v bit 1)
    const float c2 = cs[4],  s2 = cs[5];               // P=7, k=2  (v bit 2)
    const float c1 = cs[2],  s1 = cs[3];               // P=8, k=1  (pack bit)
    const float a0 = c3 * c2, a1 = s3 * c2, a2 = c3 * s2, a3 = s3 * s2;
    float fv[8];
    fv[0] = c4 * a0; fv[1] = s4 * a0; fv[2] = c4 * a1; fv[3] = s4 * a1;
    fv[4] = c4 * a2; fv[5] = s4 * a2; fv[6] = c4 * a3; fv[7] = s4 * a3;
#pragma unroll
    for (int v = 0; v < 8; ++v) {
        const float g = A * fv[v];
        X[v] = F2(make_float2(g * c1, g * s1));
        Y[v] = 0ull;
    }
}

// ---- measurement, streaming from smem ----
template<int WIRE>
__device__ __forceinline__ void measure_wire_sm(const float2* fin, unsigned lane, float* outb) {
    constexpr int P = 9 - WIRE;
    float cr = 0.f, ci = 0.f, zz = 0.f;
    if constexpr (P < 5) {
        const int bit = (lane >> P) & 1u;
        const float f0 = bit ? 0.f : 1.f;
        const float zs = bit ? -1.f : 1.f;
#pragma unroll
        for (int r = 0; r < 32; ++r) {
            float2 a = fin[r * 32 + lane];
            float px = __shfl_xor_sync(0xffffffffu, a.x, 1 << P);
            float py = __shfl_xor_sync(0xffffffffu, a.y, 1 << P);
            cr += f0 * (a.x * px + a.y * py);
            ci += f0 * (a.x * py - a.y * px);
            zz += zs * (a.x * a.x + a.y * a.y);
        }
    } else {
        constexpr int RB = P - 5;
#pragma unroll
        for (int r0 = 0; r0 < 32; ++r0) {
            if ((r0 >> RB) & 1) continue;
            float2 a0 = fin[r0 * 32 + lane];
            float2 a1 = fin[(r0 | (1 << RB)) * 32 + lane];
            cr += a0.x * a1.x + a0.y * a1.y;
            ci += a0.x * a1.y - a0.y * a1.x;
            zz += (a0.x * a0.x + a0.y * a0.y) - (a1.x * a1.x + a1.y * a1.y);
        }
    }
#pragma unroll
    for (int m = 16; m; m >>= 1) {
        cr += __shfl_xor_sync(0xffffffffu, cr, m);
        ci += __shfl_xor_sync(0xffffffffu, ci, m);
        zz += __shfl_xor_sync(0xffffffffu, zz, m);
    }
    if (lane == 0) {
        outb[WIRE]      = 2.0f * cr;
        outb[10 + WIRE] = 2.0f * ci;
        outb[20 + WIRE] = zz;
    }
}

// ---------------------------------------------------------------------------
// smem layout (bytes):
//   [0,10240)      cs_s  2560 f
//   [10240,10560)  ffcs  80 f
//   [10560,10816)  lcu_s 32 f2
//   [10816,10944)  rsum  32 f
//   [10944, ...)   UNION:
//     GEMM:  emb_s 32*513 f (65664) | W_s 40*512 f (81920)   = 147584
//     MAIN:  buf 16384 u64 (131072) | cur 1024 u64 (8192)    = 139264
// ---------------------------------------------------------------------------
#define OFF_UNION  10944
#define TOT_SMEM   (OFF_UNION + 147584)

__global__ void __launch_bounds__(NTHR, 1)
quixer_kernel(const float* __restrict__ emb, const float* __restrict__ W,
              const float* __restrict__ bias,
              const float* __restrict__ lcu_re, const float* __restrict__ lcu_im,
              const float* __restrict__ qsvt, const float* __restrict__ ffp,
              float* __restrict__ out) {
    extern __shared__ char smraw[];
    float*  cs_s  = (float*)smraw;                       // 2560 f
    float*  ffcs  = cs_s + 2560;                         // 80 f
    float2* lcu_s = (float2*)(ffcs + 80);                // 32 f2
    float*  rsum  = (float*)(lcu_s + 32);                // 32 f
    char*   un    = smraw + OFF_UNION;
    float*  emb_s = (float*)un;                          // 32*513
    float*  W_s   = emb_s + 32 * 513;                    // 40*512
    u64*    buf   = (u64*)un;                            // 16*1024 u64
    u64*    cur   = buf + 16 * 1024;                     // 1024 u64

    const int b   = blockIdx.x;
    const int tid = threadIdx.x;
    const int w   = tid >> 5;
    const unsigned lane = tid & 31u;
    const int wb    = w & 1;
    const int pair  = w >> 1;
    const int grp   = w >> 2;                 // 4-warp group 0..7
    const int gt    = tid & (GRP - 1);        // id within group
    const int pgt   = gt ^ 32;                // partner within group
    const int barid = 1 + grp;                // named bars 1..8
    ulonglong2* Eg  = (ulonglong2*)buf + grp * 1024;  // 16KB slab per group
    float*      Fg  = (float*)Eg;

    // ---------------- phase 1: GEMM + trig ----------------
    for (int i = tid; i < 32 * 512; i += NTHR) {
        int l = i >> 9, d = i & 511;
        emb_s[l * 513 + d] = emb[(b * 32 + l) * 512 + d];
    }
    for (int i = tid; i < 40 * 512; i += NTHR) W_s[i] = W[i];

    if (tid < 40) {
        float sv, cv;
        __sincosf(0.5f * ffp[tid], &sv, &cv);
        ffcs[2 * tid] = cv;
        ffcs[2 * tid + 1] = sv;
    }
    if (w == 1) {
        float re = lcu_re[lane], im = lcu_im[lane];
        float S = sqrtf(re * re + im * im);
#pragma unroll
        for (int m = 16; m; m >>= 1) S += __shfl_xor_sync(0xffffffffu, S, m);
        lcu_s[lane] = make_float2(re / S, im / S);
    }
    __syncthreads();

    if (tid < 256) {
        const int l  = tid & 31;
        const int kg = tid >> 5;             // 0..7, each handles 5 k's
        float acc5[5] = {0.f, 0.f, 0.f, 0.f, 0.f};
        const float* er = emb_s + l * 513;
        const float* wr = W_s + kg * 5 * 512;
#pragma unroll 4
        for (int d = 0; d < 512; ++d) {
            float a = er[d];
#pragma unroll
            for (int j = 0; j < 5; ++j) acc5[j] += wr[j * 512 + d] * a;
        }
#pragma unroll
        for (int j = 0; j < 5; ++j) {
            int k = kg * 5 + j;
            float th = 0.5f * (acc5[j] + bias[k]);
            float sv, cv;
            __sincosf(th, &sv, &cv);
            cs_s[l * 80 + 2 * k]     = cv;
            cs_s[l * 80 + 2 * k + 1] = sv;
        }
    }
    __syncthreads();   // cs ready; union region free for buf/cur

    // ---------------- phase 2: QSVT mainloop ----------------
    const float q0 = qsvt[0], q1 = qsvt[1], q2 = qsvt[2];
    u64 acc = (tid == 0) ? F2(make_float2(q0, 0.f)) : 0ull;

    u64 X[8], Y[8];
    const int wbp = tid >> 9;
    const int r   = tid & 511;

    for (int step = 1; step <= 2; ++step) {
        const float qk = (step == 1) ? q1 : q2;
        u64 m = 0ull;
        for (int pass = 0; pass < 2; ++pass) {
            const int l = pair + pass * 16;
            const float* csl = cs_s + l * 80;
            if (step == 1) {
                // |0> through first RY layer = product state; then gates 10..39
                build_ry_product(X, Y, csl, lane, wb);
                crx10_y0(X, Y, csl[20], csl[21], lane, Eg, gt, pgt, barid);
                run_gates<11>(X, Y, csl, lane, wb, Eg, Fg, gt, pgt, barid);
            } else {
#pragma unroll
                for (int v = 0; v < 8; ++v) {
                    X[v] = cur[wb * 512 + v * 32 + lane];
                    Y[v] = cur[wb * 512 + 256 + v * 32 + lane];
                }
                run_gates<0>(X, Y, csl, lane, wb, Eg, Fg, gt, pgt, barid);
            }
            // complex LCU scale
            const float2 lw = lcu_s[l];
            const u64 av = F2(make_float2(lw.x, lw.x));
            const u64 bp = F2(make_float2(lw.y, lw.y));
            const u64 bn = F2(make_float2(-lw.y, -lw.y));
#pragma unroll
            for (int v = 0; v < 8; ++v) {
                u64 tx = X[v];
                X[v] = fma2(bn, Y[v], mul2(av, tx));
                Y[v] = fma2(bp, tx, mul2(av, Y[v]));
            }
            __syncthreads();                 // exchanges done before buf reuse
            u64* rw = buf + w * 512;
#pragma unroll
            for (int v = 0; v < 8; ++v) {
                rw[v * 32 + lane]       = X[v];
                rw[256 + v * 32 + lane] = Y[v];
            }
            __syncthreads();
            // flat 16-way sum over pairs; 2 accumulators for ILP
            u64 a0 = buf[wbp * 512 + r];
            u64 a1 = buf[(2 + wbp) * 512 + r];
#pragma unroll
            for (int p = 2; p < 16; p += 2) {
                a0 = add2(a0, buf[(2 * p + wbp) * 512 + r]);
                a1 = add2(a1, buf[(2 * p + 2 + wbp) * 512 + r]);
            }
            u64 a = add2(a0, a1);
            m = (pass == 0) ? a : add2(m, a);
            __syncthreads();                 // before next pass reuses buf
        }
        const u64 qk2 = F2(make_float2(qk, qk));
        acc = fma2(qk2, m, acc);
        if (step == 1) {
            cur[tid] = m;
            __syncthreads();
        }
    }

    // normalize acc
    {
        float2 t0 = U2(acc);
        float p = t0.x * t0.x + t0.y * t0.y;
#pragma unroll
        for (int mm = 16; mm; mm >>= 1) p += __shfl_xor_sync(0xffffffffu, p, mm);
        if (lane == 0) rsum[w] = p;
    }
    __syncthreads();
    if (tid == 0) {
        float t = 0.f;
#pragma unroll
        for (int i = 0; i < 32; ++i) t += rsum[i];
        rsum[0] = rsqrtf(t);
    }
    __syncthreads();
    {
        const float inv = rsum[0];
        cur[tid] = mul2(acc, F2(make_float2(inv, inv)));
    }
    __syncthreads();

    // feed-forward PQC: warps 0-3 only (group 0, barid 1)
    float2* fin = (float2*)buf;
    if (w < 4) {
#pragma unroll
        for (int v = 0; v < 8; ++v) {
            X[v] = cur[wb * 512 + v * 32 + lane];
            Y[v] = cur[wb * 512 + 256 + v * 32 + lane];
        }
        run_gates<0>(X, Y, ffcs, lane, wb, Eg, Fg, gt, pgt, barid);
    }
    __syncthreads();                     // exchanges done, buf free
    if (w < 2) {
#pragma unroll
        for (int v = 0; v < 8; ++v) {
            float2 xv = U2(X[v]), yv = U2(Y[v]);
            const int r0 = wb * 16 + v;        // pack 0
            const int r1 = wb * 16 + 8 + v;    // pack 1
            fin[r0 * 32 + lane] = make_float2(xv.x, yv.x);
            fin[r1 * 32 + lane] = make_float2(xv.y, yv.y);
        }
    }
    __syncthreads();

    // measurement: warps 0..9, one wire each
    if (w < 10) {
        float* outb = out + b * 30;
        switch (w) {
            case 0: measure_wire_sm<0>(fin, lane, outb); break;
            case 1: measure_wire_sm<1>(fin, lane, outb); break;
            case 2: measure_wire_sm<2>(fin, lane, outb); break;
            case 3: measure_wire_sm<3>(fin, lane, outb); break;
            case 4: measure_wire_sm<4>(fin, lane, outb); break;
            case 5: measure_wire_sm<5>(fin, lane, outb); break;
            case 6: measure_wire_sm<6>(fin, lane, outb); break;
            case 7: measure_wire_sm<7>(fin, lane, outb); break;
            case 8: measure_wire_sm<8>(fin, lane, outb); break;
            case 9: measure_wire_sm<9>(fin, lane, outb); break;
        }
    }
}

// ---------------------------------------------------------------------------
extern "C" void kernel_launch(void* const* d_in, const int* in_sizes, int n_in,
                              void* d_out, int out_size) {
    const float* emb    = (const float*)d_in[0];
    const float* W      = (const float*)d_in[1];
    const float* bias   = (const float*)d_in[2];
    const float* lcu_re = (const float*)d_in[3];
    const float* lcu_im = (const float*)d_in[4];
    const float* qsvt   = (const float*)d_in[5];
    const float* ffp    = (const float*)d_in[6];
    float* out = (float*)d_out;

    cudaFuncSetAttribute(quixer_kernel, cudaFuncAttributeMaxDynamicSharedMemorySize, TOT_SMEM);
    quixer_kernel<<<NB, NTHR, TOT_SMEM>>>(emb, W, bias, lcu_re, lcu_im, qsvt, ffp, out);
}